// round 14
// baseline (speedup 1.0000x reference)
#include <cuda_runtime.h>
#include <cuda_fp16.h>
#include <math.h>
#include <stdint.h>

#define BB   8
#define SS   2048
#define DD   512
#define DKK  64
#define DFFN 2048
#define NREP 6
#define MSROWS (BB*SS)          // 16384
#define NTOT (BB*SS*DD)         // 8388608

typedef __half f16;

// ---------------------------------------------------------------------------
// Scratch
// ---------------------------------------------------------------------------
__device__ f16 g_xfh [NTOT];    // y2 pair (post-FFN stream / embed at it 0)
__device__ f16 g_xfl [NTOT];
__device__ f16 g_x1fh[NTOT];    // y1 pair (post-attention stream)
__device__ f16 g_x1fl[NTOT];
__device__ f16 g_qkvfh[MSROWS*192];
__device__ f16 g_headf[MSROWS*DKK];
__device__ f16 g_hf[(long)MSROWS*DFFN];

__device__ f16 g_wqkvfh[192*DD];
__device__ f16 g_wqkvfl[192*DD];
__device__ f16 g_wofh[DD*DKK];
__device__ f16 g_wofl[DD*DKK];
__device__ f16 g_w1fh[DFFN*DD];
__device__ f16 g_w1fl[DFFN*DD];
__device__ f16 g_w2fh[DD*DFFN];
__device__ f16 g_w2fl[DD*DFFN];
__device__ float g_bqkv[192];
__device__ float g_rsqkv[192];
__device__ float g_rsw1[DFFN];

__device__ float g_psum[1024];
__device__ float g_psq [1024];
__device__ float g_statsA[2];       // mid-LN (m, rs)
__device__ float g_statsB[2];       // post-LN (m, rs); seeded {0,1} by embed
__device__ int   g_cnt;             // last-CTA counter (zero-initialized)

// ---------------------------------------------------------------------------
// Helpers
// ---------------------------------------------------------------------------
__device__ __forceinline__ uint32_t cvta_shared_u32(const void* p) {
    uint32_t a;
    asm("{ .reg .u64 t; cvta.to.shared.u64 t, %1; cvt.u32.u64 %0, t; }" : "=r"(a) : "l"(p));
    return a;
}
__device__ __forceinline__ void cp_async16(uint32_t saddr, const void* gptr) {
    asm volatile("cp.async.cg.shared.global [%0], [%1], 16;" :: "r"(saddr), "l"(gptr));
}
__device__ __forceinline__ void cp_commit() {
    asm volatile("cp.async.commit_group;" ::: "memory");
}
template<int N>
__device__ __forceinline__ void cp_wait() {
    asm volatile("cp.async.wait_group %0;" :: "n"(N) : "memory");
}
__device__ __forceinline__ void ldsm_x4(uint32_t& r0, uint32_t& r1, uint32_t& r2, uint32_t& r3,
                                        uint32_t addr) {
    asm volatile("ldmatrix.sync.aligned.m8n8.x4.shared.b16 {%0,%1,%2,%3}, [%4];"
                 : "=r"(r0), "=r"(r1), "=r"(r2), "=r"(r3) : "r"(addr));
}
__device__ __forceinline__ void ldsm_x4_t(uint32_t& r0, uint32_t& r1, uint32_t& r2, uint32_t& r3,
                                          uint32_t addr) {
    asm volatile("ldmatrix.sync.aligned.m8n8.x4.trans.shared.b16 {%0,%1,%2,%3}, [%4];"
                 : "=r"(r0), "=r"(r1), "=r"(r2), "=r"(r3) : "r"(addr));
}
__device__ __forceinline__ uint32_t pack_f16(float e0, float e1) {
    uint32_t r;
    asm("cvt.rn.f16x2.f32 %0, %1, %2;" : "=r"(r) : "f"(e1), "f"(e0));
    return r;
}
__device__ __forceinline__ void split_f16p(float e0, float e1, uint32_t& hi, uint32_t& lo) {
    f16 h0 = __float2half_rn(e0);
    f16 h1 = __float2half_rn(e1);
    float l0 = e0 - __half2float(h0);
    float l1 = e1 - __half2float(h1);
    hi = ((uint32_t)__half_as_ushort(h1) << 16) | __half_as_ushort(h0);
    lo = pack_f16(l0, l1);
}
__device__ __forceinline__ void mma_f16(float* c, const uint32_t* a, const uint32_t* b) {
    asm volatile(
        "mma.sync.aligned.m16n8k16.row.col.f32.f16.f16.f32 "
        "{%0,%1,%2,%3}, {%4,%5,%6,%7}, {%8,%9}, {%0,%1,%2,%3};"
        : "+f"(c[0]), "+f"(c[1]), "+f"(c[2]), "+f"(c[3])
        : "r"(a[0]), "r"(a[1]), "r"(a[2]), "r"(a[3]), "r"(b[0]), "r"(b[1]));
}

#define SMSB 40

// ---------------------------------------------------------------------------
// Unified 2-term fp16 GEMM with LN folding.
// MODE 0: v = raw + bias + (src pair - m_res)*rs_res -> pair out + LN partials;
//         LAST CTA reduces partials -> stats_out (device-side finalize).
// MODE 1: v = (raw - m_in*rowsum[col])*rs_in + bias, ReLU -> single out
// MODE 2: v = (raw - m_in*rowsum[col])*rs_in + bias -> pair out
// MODE 3: v = (raw - m_in*rowsum[col])*rs_in + bias -> single out (no ReLU)
// ---------------------------------------------------------------------------
template<int BN, int WM, int WN, int MODE>
__global__ void __launch_bounds__(256, 2)
gemm2(const f16* __restrict__ Af, int lda,
      const f16* __restrict__ Bh, const f16* __restrict__ Bl, int ldb,
      const float* __restrict__ bias,
      const float* __restrict__ instats, const float* __restrict__ rowsum,
      const f16* __restrict__ srch, const f16* __restrict__ srcl,
      const float* __restrict__ resstats,
      f16* __restrict__ Cf, f16* __restrict__ Cfl,
      int ldc, int K, float alpha,
      float* __restrict__ psum, float* __restrict__ psq,
      float* __restrict__ stats_out, int* __restrict__ cnt)
{
    constexpr int MT = WM / 16;
    constexpr int NT = WN / 8;
    constexpr int WARPS_N = BN / WN;
    static_assert((128 / WM) * (BN / WN) == 8, "8 warps");
    static_assert(NT % 2 == 0, "NT even");
    constexpr int STAGES = 3;
    constexpr int OFF_BH = 128 * SMSB;
    constexpr int OFF_BL = OFF_BH + BN * SMSB;
    constexpr int BUFSZ  = OFF_BL + BN * SMSB;
    constexpr int BITER  = (BN * 4) / 256;

    extern __shared__ f16 smemf[];
    __shared__ float s_red0[256];
    __shared__ float s_red1[256];
    __shared__ int s_last;

    const int tid  = threadIdx.x;
    const int lane = tid & 31;
    const int wid  = tid >> 5;
    const int warp_m = wid / WARPS_N;
    const int warp_n = wid % WARPS_N;
    const int qr = lane >> 2;
    const int qc = lane & 3;

    const int m0 = blockIdx.y * 128;
    const int n0 = blockIdx.x * BN;

    float acc[MT][NT][4];
#pragma unroll
    for (int i = 0; i < MT; i++)
#pragma unroll
        for (int j = 0; j < NT; j++)
#pragma unroll
            for (int u = 0; u < 4; u++) acc[i][j][u] = 0.f;

    const uint32_t sb = cvta_shared_u32(smemf);

    auto load_chunk = [&](int c, int stg) {
        const int k0 = c << 5;
        const uint32_t base = sb + (uint32_t)stg * (BUFSZ * 2);
#pragma unroll
        for (int i = 0; i < 2; i++) {
            int idx = tid + i * 256;
            int row = idx >> 2, c8 = idx & 3;
            long g = (long)(m0 + row) * lda + k0 + c8 * 8;
            uint32_t so = (uint32_t)(row * SMSB + c8 * 8) * 2;
            cp_async16(base + so, Af + g);
        }
#pragma unroll
        for (int i = 0; i < BITER; i++) {
            int idx = tid + i * 256;
            int row = idx >> 2, c8 = idx & 3;
            long g = (long)(n0 + row) * ldb + k0 + c8 * 8;
            uint32_t so = (uint32_t)(row * SMSB + c8 * 8) * 2;
            cp_async16(base + OFF_BH * 2 + so, Bh + g);
            cp_async16(base + OFF_BL * 2 + so, Bl + g);
        }
    };

    const int nch = K >> 5;
#pragma unroll
    for (int s = 0; s < STAGES - 1; s++) { load_chunk(s, s); cp_commit(); }

    const uint32_t a_off = (uint32_t)(((lane & 15) + warp_m * WM) * SMSB + (lane >> 4) * 8) * 2;
    const uint32_t b_off = (uint32_t)((((lane >> 4) & 1) * 8 + (lane & 7) + warp_n * WN) * SMSB
                                      + ((lane >> 3) & 1) * 8) * 2;

    for (int c = 0; c < nch; c++) {
        const int stg = c % STAGES;
        if (c + STAGES - 1 < nch) {
            load_chunk(c + STAGES - 1, (c + STAGES - 1) % STAGES);
            cp_commit();
            cp_wait<STAGES - 1>();
        } else {
            cp_wait<0>();
        }
        __syncthreads();

        const uint32_t stA  = sb + (uint32_t)stg * (BUFSZ * 2);
        const uint32_t stBh = stA + OFF_BH * 2;
        const uint32_t stBl = stA + OFF_BL * 2;

#pragma unroll
        for (int ks = 0; ks < 2; ks++) {
            const uint32_t kk2 = (uint32_t)ks * 32;
            uint32_t bh[NT][2], bl[NT][2];
#pragma unroll
            for (int in2 = 0; in2 < NT / 2; in2++) {
                uint32_t off = b_off + (uint32_t)in2 * (16 * SMSB * 2) + kk2;
                ldsm_x4(bh[2*in2][0], bh[2*in2][1], bh[2*in2+1][0], bh[2*in2+1][1], stBh + off);
                ldsm_x4(bl[2*in2][0], bl[2*in2][1], bl[2*in2+1][0], bl[2*in2+1][1], stBl + off);
            }
#pragma unroll
            for (int im = 0; im < MT; im++) {
                uint32_t off = a_off + (uint32_t)im * (16 * SMSB * 2) + kk2;
                uint32_t ah[4];
                ldsm_x4(ah[0], ah[1], ah[2], ah[3], stA + off);
#pragma unroll
                for (int in_ = 0; in_ < NT; in_++) {
                    mma_f16(acc[im][in_], ah, bh[in_]);
                    mma_f16(acc[im][in_], ah, bl[in_]);
                }
            }
        }
        __syncthreads();
    }

    // ---- epilogue ----
    float m_in = 0.f, rs_in = 1.f, m_res = 0.f, rs_res = 1.f;
    if (MODE == 1 || MODE == 2 || MODE == 3) { m_in = instats[0]; rs_in = instats[1]; }
    if (MODE == 0) { m_res = resstats[0]; rs_res = resstats[1]; }

    float lsum = 0.f, lsq = 0.f;
#pragma unroll
    for (int im = 0; im < MT; im++) {
#pragma unroll
        for (int h2 = 0; h2 < 2; h2++) {
            const int row = m0 + warp_m * WM + im * 16 + qr + h2 * 8;
#pragma unroll
            for (int in_ = 0; in_ < NT; in_++) {
                const int col = n0 + warp_n * WN + in_ * 8 + qc * 2;
                float raw0 = acc[im][in_][h2 * 2 + 0] * alpha;
                float raw1 = acc[im][in_][h2 * 2 + 1] * alpha;
                if (MODE == 0) {
                    long si = (long)row * ldc + col;
                    float y0 = __half2float(srch[si])     + __half2float(srcl[si]);
                    float y1 = __half2float(srch[si + 1]) + __half2float(srcl[si + 1]);
                    float v0 = raw0 + bias[col]     + (y0 - m_res) * rs_res;
                    float v1 = raw1 + bias[col + 1] + (y1 - m_res) * rs_res;
                    uint32_t hp, lp;
                    split_f16p(v0, v1, hp, lp);
                    *reinterpret_cast<uint32_t*>(&Cf [(long)row * ldc + col]) = hp;
                    *reinterpret_cast<uint32_t*>(&Cfl[(long)row * ldc + col]) = lp;
                    lsum += v0 + v1;
                    lsq  += v0 * v0 + v1 * v1;
                } else {
                    float v0 = (raw0 - m_in * rowsum[col])     * rs_in + bias[col];
                    float v1 = (raw1 - m_in * rowsum[col + 1]) * rs_in + bias[col + 1];
                    if (MODE == 1) {
                        v0 = fmaxf(v0, 0.f); v1 = fmaxf(v1, 0.f);
                        *reinterpret_cast<uint32_t*>(&Cf[(long)row * ldc + col]) = pack_f16(v0, v1);
                    } else if (MODE == 3) {
                        *reinterpret_cast<uint32_t*>(&Cf[(long)row * ldc + col]) = pack_f16(v0, v1);
                    } else {
                        uint32_t hp, lp;
                        split_f16p(v0, v1, hp, lp);
                        *reinterpret_cast<uint32_t*>(&Cf [(long)row * ldc + col]) = hp;
                        *reinterpret_cast<uint32_t*>(&Cfl[(long)row * ldc + col]) = lp;
                    }
                }
            }
        }
    }

    if (MODE == 0) {
        s_red0[tid] = lsum; s_red1[tid] = lsq;
        __syncthreads();
        for (int s = 128; s > 0; s >>= 1) {
            if (tid < s) { s_red0[tid] += s_red0[tid + s]; s_red1[tid] += s_red1[tid + s]; }
            __syncthreads();
        }
        const int ncta = gridDim.x * gridDim.y;
        if (tid == 0) {
            int cta = blockIdx.y * gridDim.x + blockIdx.x;
            psum[cta] = s_red0[0];
            psq [cta] = s_red1[0];
            __threadfence();
            int v = atomicAdd(cnt, 1);
            s_last = (v == ncta - 1);
        }
        __syncthreads();
        if (s_last) {
            // ONE CTA reduces all partials -> stats
            double a = 0.0, b = 0.0;
            for (int i = tid; i < ncta; i += 256) {
                a += (double)psum[i];
                b += (double)psq[i];
            }
            __shared__ double ds[256], dq[256];
            ds[tid] = a; dq[tid] = b;
            __syncthreads();
            for (int s = 128; s > 0; s >>= 1) {
                if (tid < s) { ds[tid] += ds[tid + s]; dq[tid] += dq[tid + s]; }
                __syncthreads();
            }
            if (tid == 0) {
                double m = ds[0] / (double)NTOT;
                double vv = dq[0] / (double)NTOT - m * m;
                stats_out[0] = (float)m;
                stats_out[1] = (float)(1.0 / sqrt(vv + 1e-5));
                __threadfence();
                *cnt = 0;
            }
        }
    }
}

// ---------------------------------------------------------------------------
// Flash attention (single-limb K/V; validated R13)
// ---------------------------------------------------------------------------
#define FAS 72

__global__ void __launch_bounds__(256, 2)
flash_attn(const f16* __restrict__ qkvfh, f16* __restrict__ headf, float alpha)
{
    constexpr int QSZ = 64 * FAS;
    constexpr int CSZ = 64 * FAS;

    extern __shared__ f16 fsm[];
    const uint32_t sb = cvta_shared_u32(fsm);
    const uint32_t q_a  = sb;
    const uint32_t ck_a = sb + QSZ * 2;   // 2 bufs x {kh, vh}

    const int tid  = threadIdx.x;
    const int lane = tid & 31;
    const int wid  = tid >> 5;
    const int wrow  = wid & 3;
    const int khalf = wid >> 2;
    const int qr = lane >> 2, qc = lane & 3;
    const long bz = blockIdx.y;
    const long grow0 = bz * SS + blockIdx.x * 64;

#pragma unroll
    for (int i = 0; i < 2; i++) {
        int idx = tid + i * 256;
        int r = idx >> 3, s = idx & 7;
        long g = (grow0 + r) * 192 + s * 8;
        cp_async16(q_a + (uint32_t)(r * FAS + s * 8) * 2, qkvfh + g);
    }
    cp_commit();

    auto load_chunk = [&](int c, int buf) {
        const uint32_t base = ck_a + (uint32_t)buf * 2 * CSZ * 2;
#pragma unroll
        for (int i = 0; i < 2; i++) {
            int idx = tid + i * 256;
            int r = idx >> 3, s = idx & 7;
            long g = (bz * SS + c * 64 + r) * 192 + s * 8;
            uint32_t so = (uint32_t)(r * FAS + s * 8) * 2;
            cp_async16(base + so,           qkvfh + g + 64);
            cp_async16(base + CSZ * 2 + so, qkvfh + g + 128);
        }
        cp_commit();
    };

    load_chunk(0, 0);
    cp_wait<1>();
    __syncthreads();

    const uint32_t qa_off = (uint32_t)((lane & 15) + wrow * 16) * (FAS * 2) + (lane >> 4) * 16;
    uint32_t qa[4][4];
#pragma unroll
    for (int ks = 0; ks < 4; ks++)
        ldsm_x4(qa[ks][0], qa[ks][1], qa[ks][2], qa[ks][3], q_a + qa_off + ks * 32);

    const uint32_t kb_off = (uint32_t)(khalf * 32 + ((lane >> 4) & 1) * 8 + (lane & 7)) * (FAS * 2)
                            + ((lane >> 3) & 1) * 16;
    const uint32_t vb_off = (uint32_t)(khalf * 32 + (lane & 7) + ((lane >> 3) & 1) * 8) * (FAS * 2)
                            + ((lane >> 4) & 1) * 16;

    float o[8][4];
#pragma unroll
    for (int t = 0; t < 8; t++)
#pragma unroll
        for (int u = 0; u < 4; u++) o[t][u] = 0.f;
    float rs0 = 0.f, rs1 = 0.f;

    for (int c = 0; c < SS / 64; c++) {
        const int buf = c & 1;
        cp_wait<0>();
        __syncthreads();
        if (c + 1 < SS / 64) load_chunk(c + 1, buf ^ 1);

        const uint32_t kh_a = ck_a + (uint32_t)buf * 2 * CSZ * 2;
        const uint32_t vh_a = kh_a + CSZ * 2;

        float s[4][4];
#pragma unroll
        for (int j = 0; j < 4; j++)
#pragma unroll
            for (int u = 0; u < 4; u++) s[j][u] = 0.f;

#pragma unroll
        for (int ks = 0; ks < 4; ks++) {
            uint32_t kbh[4][2];
#pragma unroll
            for (int j4 = 0; j4 < 2; j4++) {
                uint32_t off = kb_off + (uint32_t)j4 * (16 * FAS * 2) + ks * 32;
                ldsm_x4(kbh[2*j4][0], kbh[2*j4][1], kbh[2*j4+1][0], kbh[2*j4+1][1], kh_a + off);
            }
#pragma unroll
            for (int j = 0; j < 4; j++)
                mma_f16(s[j], qa[ks], kbh[j]);
        }

        uint32_t pa[2][4];
#pragma unroll
        for (int j = 0; j < 4; j++) {
            float p0 = __expf(s[j][0] * alpha);
            float p1 = __expf(s[j][1] * alpha);
            float p2 = __expf(s[j][2] * alpha);
            float p3 = __expf(s[j][3] * alpha);
            rs0 += p0 + p1;
            rs1 += p2 + p3;
            int ks2 = j >> 1, half = (j & 1) * 2;
            pa[ks2][half + 0] = pack_f16(p0, p1);
            pa[ks2][half + 1] = pack_f16(p2, p3);
        }

#pragma unroll
        for (int ks = 0; ks < 2; ks++) {
            uint32_t vbh[8][2];
#pragma unroll
            for (int i = 0; i < 4; i++) {
                uint32_t off = vb_off + (uint32_t)ks * (16 * FAS * 2) + i * 32;
                ldsm_x4_t(vbh[2*i][0], vbh[2*i][1], vbh[2*i+1][0], vbh[2*i+1][1], vh_a + off);
            }
#pragma unroll
            for (int t = 0; t < 8; t++)
                mma_f16(o[t], pa[ks], vbh[t]);
        }
    }

    rs0 += __shfl_xor_sync(0xffffffffu, rs0, 1);
    rs0 += __shfl_xor_sync(0xffffffffu, rs0, 2);
    rs1 += __shfl_xor_sync(0xffffffffu, rs1, 1);
    rs1 += __shfl_xor_sync(0xffffffffu, rs1, 2);

    __syncthreads();
    float* sof = reinterpret_cast<float*>(fsm + QSZ);
    float4* sof4 = reinterpret_cast<float4*>(sof);
    float* zf = sof + 4 * 8 * 32 * 4;

    if (wid >= 4) {
        int base = (wid - 4) * 256;
#pragma unroll
        for (int t = 0; t < 8; t++) {
            float4 v; v.x = o[t][0]; v.y = o[t][1]; v.z = o[t][2]; v.w = o[t][3];
            sof4[base + t * 32 + lane] = v;
        }
        if (qc == 0) {
            zf[(wid - 4) * 16 + qr]     = rs0;
            zf[(wid - 4) * 16 + qr + 8] = rs1;
        }
    }
    __syncthreads();
    if (wid < 4) {
        int base = wid * 256;
#pragma unroll
        for (int t = 0; t < 8; t++) {
            float4 v = sof4[base + t * 32 + lane];
            o[t][0] += v.x; o[t][1] += v.y; o[t][2] += v.z; o[t][3] += v.w;
        }
        rs0 += zf[wid * 16 + qr];
        rs1 += zf[wid * 16 + qr + 8];
        float inv0 = 1.0f / rs0;
        float inv1 = 1.0f / rs1;
        long g0 = grow0 + wid * 16 + qr;
#pragma unroll
        for (int t = 0; t < 8; t++) {
            int col = t * 8 + qc * 2;
            *reinterpret_cast<uint32_t*>(&headf[g0 * DKK + col]) =
                pack_f16(o[t][0] * inv0, o[t][1] * inv0);
            *reinterpret_cast<uint32_t*>(&headf[(g0 + 8) * DKK + col]) =
                pack_f16(o[t][2] * inv1, o[t][3] * inv1);
        }
    }
}

// ---------------------------------------------------------------------------
// Weight prep
// ---------------------------------------------------------------------------
__device__ __forceinline__ void wsplit(float w, f16& oh, f16& ol) {
    f16 h = __float2half_rn(w);
    oh = __float2half_rn(__half2float(h) * 1024.0f);
    ol = __float2half_rn((w - __half2float(h)) * 1024.0f);
}

__global__ void transpose_split_f16(const float* __restrict__ in,
                                    f16* __restrict__ oh, f16* __restrict__ ol,
                                    int R, int C_) {
    __shared__ float tt[32][33];
    int r0 = blockIdx.y * 32, c0 = blockIdx.x * 32;
#pragma unroll
    for (int i = 0; i < 32; i += 8)
        tt[threadIdx.y + i][threadIdx.x] = in[(long)(r0 + threadIdx.y + i) * C_ + c0 + threadIdx.x];
    __syncthreads();
#pragma unroll
    for (int i = 0; i < 32; i += 8) {
        long o = (long)(c0 + threadIdx.y + i) * R + r0 + threadIdx.x;
        wsplit(tt[threadIdx.x][threadIdx.y + i], oh[o], ol[o]);
    }
}

__global__ void colsum_kernel(const float* __restrict__ W, float* __restrict__ out,
                              int K, int N) {
    int n = blockIdx.x * 256 + threadIdx.x;
    if (n >= N) return;
    float s = 0.f;
    for (int k = 0; k < K; k++) s += W[(long)k * N + n];
    out[n] = s;
}

__global__ void prep_qkvw(const float* __restrict__ Wq, const float* __restrict__ Wk,
                          const float* __restrict__ Wv, const float* __restrict__ bq,
                          const float* __restrict__ bk, const float* __restrict__ bv) {
    int idx = blockIdx.x * 256 + threadIdx.x;
    if (idx < 192 * DD) {
        int n = idx >> 9, k = idx & 511;
        const float* W = (n < 64) ? Wq : ((n < 128) ? Wk : Wv);
        float v = W[k * DKK + (n & 63)];
        wsplit(v, g_wqkvfh[idx], g_wqkvfl[idx]);
    }
    if (idx < 192) {
        g_bqkv[idx] = (idx < 64) ? bq[idx] : ((idx < 128) ? bk[idx - 64] : bv[idx - 128]);
        const float* W = (idx < 64) ? Wq : ((idx < 128) ? Wk : Wv);
        float s = 0.f;
        for (int k = 0; k < DD; k++) s += W[k * DKK + (idx & 63)];
        g_rsqkv[idx] = s;
    }
    if (idx == 0) g_cnt = 0;
}

__global__ void prep_wo(const float* __restrict__ Wo) {
    int idx = blockIdx.x * 256 + threadIdx.x;
    if (idx >= DD * DKK) return;
    int e = idx / DKK, t = idx % DKK;
    float s = 0.f;
#pragma unroll
    for (int j = 0; j < 8; j++) s += Wo[(j * DKK + t) * DD + e];
    wsplit(s, g_wofh[idx], g_wofl[idx]);
}

// ---------------------------------------------------------------------------
// Embedding + positional encoding -> y2 pair; seeds identity stats
// ---------------------------------------------------------------------------
__global__ void embed_kernel(const int* __restrict__ ids, const float* __restrict__ emb) {
    long i2 = (long)blockIdx.x * 256 + threadIdx.x;
    if (blockIdx.x == 0 && threadIdx.x == 0) {
        g_statsB[0] = 0.0f;
        g_statsB[1] = 1.0f;
    }
    if (i2 >= NTOT / 2) return;
    long e = i2 * 2;
    int d  = (int)(e & (DD - 1));
    int bs = (int)(e >> 9);
    int s  = bs & (SS - 1);
    int id = ids[bs];
    float v0 = 0.f, v1 = 0.f;
    if (id != 0) {
        const float* er = emb + (long)id * DD;
        v0 = er[d]; v1 = er[d + 1];
    }
    double f0 = pow(10000.0, (double)d / 256.0);
    double f1 = pow(10000.0, (double)(d + 1) / 256.0);
    v0 += sinf((float)((double)s / f0));
    v1 += cosf((float)((double)s / f1));
    uint32_t hp, lp;
    split_f16p(v0, v1, hp, lp);
    *reinterpret_cast<uint32_t*>(&g_xfh[e]) = hp;
    *reinterpret_cast<uint32_t*>(&g_xfl[e]) = lp;
}

// ---------------------------------------------------------------------------
// Final output: out = (yh + yl - m) * rs  (fp32)
// ---------------------------------------------------------------------------
__global__ void normalize_out(const f16* __restrict__ yh, const f16* __restrict__ yl,
                              const float* __restrict__ stats, float* __restrict__ out) {
    long i2 = (long)blockIdx.x * 256 + threadIdx.x;
    long e = i2 * 2;
    if (e >= NTOT) return;
    float m = stats[0], rs = stats[1];
    float y0 = __half2float(yh[e])     + __half2float(yl[e]);
    float y1 = __half2float(yh[e + 1]) + __half2float(yl[e + 1]);
    float2 o; o.x = (y0 - m) * rs; o.y = (y1 - m) * rs;
    *reinterpret_cast<float2*>(&out[e]) = o;
}

// ---------------------------------------------------------------------------
// Launch
// ---------------------------------------------------------------------------
extern "C" void kernel_launch(void* const* d_in, const int* in_sizes, int n_in,
                              void* d_out, int out_size)
{
    const int*   ids = (const int*)  d_in[0];
    const float* emb = (const float*)d_in[1];
    const float* Wq  = (const float*)d_in[2];
    const float* bq  = (const float*)d_in[3];
    const float* Wk  = (const float*)d_in[4];
    const float* bk  = (const float*)d_in[5];
    const float* Wv  = (const float*)d_in[6];
    const float* bv  = (const float*)d_in[7];
    const float* Wo  = (const float*)d_in[8];
    const float* bo  = (const float*)d_in[9];
    const float* W1  = (const float*)d_in[10];
    const float* b1  = (const float*)d_in[11];
    const float* W2  = (const float*)d_in[12];
    const float* b2  = (const float*)d_in[13];

    float *bqkv, *rsqkv, *rsw1, *psum, *psq, *statsA, *statsB;
    int *cnt;
    f16 *xfh, *xfl, *x1fh, *x1fl, *qkvfh, *headf, *hf;
    f16 *wqkvfh, *wqkvfl, *wofh, *wofl, *w1fh, *w1fl, *w2fh, *w2fl;
    cudaGetSymbolAddress((void**)&xfh,    g_xfh);
    cudaGetSymbolAddress((void**)&xfl,    g_xfl);
    cudaGetSymbolAddress((void**)&x1fh,   g_x1fh);
    cudaGetSymbolAddress((void**)&x1fl,   g_x1fl);
    cudaGetSymbolAddress((void**)&qkvfh,  g_qkvfh);
    cudaGetSymbolAddress((void**)&headf,  g_headf);
    cudaGetSymbolAddress((void**)&hf,     g_hf);
    cudaGetSymbolAddress((void**)&wqkvfh, g_wqkvfh);
    cudaGetSymbolAddress((void**)&wqkvfl, g_wqkvfl);
    cudaGetSymbolAddress((void**)&wofh,   g_wofh);
    cudaGetSymbolAddress((void**)&wofl,   g_wofl);
    cudaGetSymbolAddress((void**)&w1fh,   g_w1fh);
    cudaGetSymbolAddress((void**)&w1fl,   g_w1fl);
    cudaGetSymbolAddress((void**)&w2fh,   g_w2fh);
    cudaGetSymbolAddress((void**)&w2fl,   g_w2fl);
    cudaGetSymbolAddress((void**)&bqkv,   g_bqkv);
    cudaGetSymbolAddress((void**)&rsqkv,  g_rsqkv);
    cudaGetSymbolAddress((void**)&rsw1,   g_rsw1);
    cudaGetSymbolAddress((void**)&psum,   g_psum);
    cudaGetSymbolAddress((void**)&psq,    g_psq);
    cudaGetSymbolAddress((void**)&statsA, g_statsA);
    cudaGetSymbolAddress((void**)&statsB, g_statsB);
    cudaGetSymbolAddress((void**)&cnt,    g_cnt);

    const int SM128 = 3 * (128 + 256) * SMSB * 2;    // 92160
    const int SM64  = 3 * (128 + 128) * SMSB * 2;    // 61440
    const int SMFA  = (64 * FAS + 4 * 64 * FAS) * 2; // 46080

    cudaFuncSetAttribute((const void*)gemm2<64, 32, 32, 3>,
                         cudaFuncAttributeMaxDynamicSharedMemorySize, SM64);
    cudaFuncSetAttribute((const void*)gemm2<128, 64, 32, 0>,
                         cudaFuncAttributeMaxDynamicSharedMemorySize, SM128);
    cudaFuncSetAttribute((const void*)gemm2<128, 64, 32, 1>,
                         cudaFuncAttributeMaxDynamicSharedMemorySize, SM128);
    cudaFuncSetAttribute((const void*)flash_attn,
                         cudaFuncAttributeMaxDynamicSharedMemorySize, SMFA);

    const float inv_div = 1.0f / 32.0f;
    const float inv_ws  = 1.0f / 1024.0f;
    dim3 tb(32, 8);

    // ---- weight prep ----
    prep_qkvw<<<(192 * DD + 255) / 256, 256>>>(Wq, Wk, Wv, bq, bk, bv);
    prep_wo<<<(DD * DKK + 255) / 256, 256>>>(Wo);
    transpose_split_f16<<<dim3(DFFN / 32, DD / 32), tb>>>(W1, w1fh, w1fl, DD, DFFN);
    transpose_split_f16<<<dim3(DD / 32, DFFN / 32), tb>>>(W2, w2fh, w2fl, DFFN, DD);
    colsum_kernel<<<DFFN / 256, 256>>>(W1, rsw1, DD, DFFN);

    embed_kernel<<<NTOT / 512, 256>>>(ids, emb);

    for (int it = 0; it < NREP; it++) {
        // QKV (norm_B folded): single-limb output (flash only reads hi)
        gemm2<64, 32, 32, 3><<<dim3(3, 128, 1), 256, SM64>>>(
            xfh, DD, wqkvfh, wqkvfl, DD, bqkv, statsB, rsqkv,
            0, 0, 0, qkvfh, 0, 192, DD, inv_ws, 0, 0, 0, 0);

        // flash attention (single-limb K/V)
        flash_attn<<<dim3(SS / 64, BB), 256, SMFA>>>(qkvfh, headf, inv_div);

        // y1 = head @ Wo_eff + bo + norm_B(y2-pair) -> pair + statsA (device finalize)
        gemm2<128, 64, 32, 0><<<dim3(4, 128, 1), 256, SM128>>>(
            headf, DKK, wofh, wofl, DKK, bo, 0, 0,
            xfh, xfl, statsB, x1fh, x1fl, DD, DKK, inv_ws, psum, psq, statsA, cnt);

        // h = relu(norm_A(y1) @ W1 + b1)
        gemm2<128, 64, 32, 1><<<dim3(16, 128, 1), 256, SM128>>>(
            x1fh, DD, w1fh, w1fl, DD, b1, statsA, rsw1,
            0, 0, 0, hf, 0, DFFN, DD, inv_ws, 0, 0, 0, 0);

        // y2 = h @ W2 + b2 + norm_A(y1-pair) -> pair + statsB (device finalize)
        gemm2<128, 64, 32, 0><<<dim3(4, 128, 1), 256, SM128>>>(
            hf, DFFN, w2fh, w2fl, DFFN, b2, 0, 0,
            x1fh, x1fl, statsA, xfh, xfl, DD, DFFN, inv_ws, psum, psq, statsB, cnt);

        finalize_launch_guard: ;
    }

    normalize_out<<<NTOT / 512, 256>>>(xfh, xfl, statsB, (float*)d_out);
}

// round 15
// speedup vs baseline: 1.0180x; 1.0180x over previous
#include <cuda_runtime.h>
#include <cuda_fp16.h>
#include <math.h>
#include <stdint.h>

#define BB   8
#define SS   2048
#define DD   512
#define DKK  64
#define DFFN 2048
#define NREP 6
#define MSROWS (BB*SS)          // 16384
#define NTOT (BB*SS*DD)         // 8388608

typedef __half f16;

// ---------------------------------------------------------------------------
// Scratch
// ---------------------------------------------------------------------------
__device__ f16 g_xfh [NTOT];    // y2 pair (post-FFN stream / embed at it 0)
__device__ f16 g_xfl [NTOT];
__device__ f16 g_x1fh[NTOT];    // y1 pair (post-attention stream)
__device__ f16 g_x1fl[NTOT];
__device__ f16 g_qkvfh[MSROWS*192];
__device__ f16 g_headf[MSROWS*DKK];
__device__ f16 g_hf[(long)MSROWS*DFFN];

__device__ f16 g_wqkvfh[192*DD];
__device__ f16 g_wqkvfl[192*DD];
__device__ f16 g_wofh[DD*DKK];
__device__ f16 g_wofl[DD*DKK];
__device__ f16 g_w1fh[DFFN*DD];
__device__ f16 g_w1fl[DFFN*DD];
__device__ f16 g_w2fh[DD*DFFN];
__device__ f16 g_w2fl[DD*DFFN];
__device__ float g_bqkv[192];
__device__ float g_rsqkv[192];      // per-output-col sum of combined QKV weight
__device__ float g_rsw1[DFFN];      // colsum of W1

__device__ float g_psum[1024];
__device__ float g_psq [1024];
__device__ float g_statsA[2];       // mid-LN (m, rs)
__device__ float g_statsB[2];       // post-LN (m, rs); seeded {0,1} by embed

// ---------------------------------------------------------------------------
// Helpers
// ---------------------------------------------------------------------------
__device__ __forceinline__ uint32_t cvta_shared_u32(const void* p) {
    uint32_t a;
    asm("{ .reg .u64 t; cvta.to.shared.u64 t, %1; cvt.u32.u64 %0, t; }" : "=r"(a) : "l"(p));
    return a;
}
__device__ __forceinline__ void cp_async16(uint32_t saddr, const void* gptr) {
    asm volatile("cp.async.cg.shared.global [%0], [%1], 16;" :: "r"(saddr), "l"(gptr));
}
__device__ __forceinline__ void cp_commit() {
    asm volatile("cp.async.commit_group;" ::: "memory");
}
template<int N>
__device__ __forceinline__ void cp_wait() {
    asm volatile("cp.async.wait_group %0;" :: "n"(N) : "memory");
}
__device__ __forceinline__ void ldsm_x4(uint32_t& r0, uint32_t& r1, uint32_t& r2, uint32_t& r3,
                                        uint32_t addr) {
    asm volatile("ldmatrix.sync.aligned.m8n8.x4.shared.b16 {%0,%1,%2,%3}, [%4];"
                 : "=r"(r0), "=r"(r1), "=r"(r2), "=r"(r3) : "r"(addr));
}
__device__ __forceinline__ void ldsm_x4_t(uint32_t& r0, uint32_t& r1, uint32_t& r2, uint32_t& r3,
                                          uint32_t addr) {
    asm volatile("ldmatrix.sync.aligned.m8n8.x4.trans.shared.b16 {%0,%1,%2,%3}, [%4];"
                 : "=r"(r0), "=r"(r1), "=r"(r2), "=r"(r3) : "r"(addr));
}
__device__ __forceinline__ uint32_t pack_f16(float e0, float e1) {
    uint32_t r;
    asm("cvt.rn.f16x2.f32 %0, %1, %2;" : "=r"(r) : "f"(e1), "f"(e0));
    return r;
}
__device__ __forceinline__ void split_f16p(float e0, float e1, uint32_t& hi, uint32_t& lo) {
    f16 h0 = __float2half_rn(e0);
    f16 h1 = __float2half_rn(e1);
    float l0 = e0 - __half2float(h0);
    float l1 = e1 - __half2float(h1);
    hi = ((uint32_t)__half_as_ushort(h1) << 16) | __half_as_ushort(h0);
    lo = pack_f16(l0, l1);
}
__device__ __forceinline__ void mma_f16(float* c, const uint32_t* a, const uint32_t* b) {
    asm volatile(
        "mma.sync.aligned.m16n8k16.row.col.f32.f16.f16.f32 "
        "{%0,%1,%2,%3}, {%4,%5,%6,%7}, {%8,%9}, {%0,%1,%2,%3};"
        : "+f"(c[0]), "+f"(c[1]), "+f"(c[2]), "+f"(c[3])
        : "r"(a[0]), "r"(a[1]), "r"(a[2]), "r"(a[3]), "r"(b[0]), "r"(b[1]));
}

#define SMSB 40

// ---------------------------------------------------------------------------
// Unified 2-term fp16 GEMM with LN folding.
// MODE 0: v = raw + bias + (src pair - m_res)*rs_res -> pair out + LN partials
// MODE 1: v = (raw - m_in*rowsum[col])*rs_in + bias, ReLU -> single out
// MODE 3: v = (raw - m_in*rowsum[col])*rs_in + bias -> single out (no ReLU)
// ---------------------------------------------------------------------------
template<int BN, int WM, int WN, int MODE>
__global__ void __launch_bounds__(256, 2)
gemm2(const f16* __restrict__ Af, int lda,
      const f16* __restrict__ Bh, const f16* __restrict__ Bl, int ldb,
      const float* __restrict__ bias,
      const float* __restrict__ instats, const float* __restrict__ rowsum,
      const f16* __restrict__ srch, const f16* __restrict__ srcl,
      const float* __restrict__ resstats,
      f16* __restrict__ Cf, f16* __restrict__ Cfl,
      int ldc, int K, float alpha,
      float* __restrict__ psum, float* __restrict__ psq)
{
    constexpr int MT = WM / 16;
    constexpr int NT = WN / 8;
    constexpr int WARPS_N = BN / WN;
    static_assert((128 / WM) * (BN / WN) == 8, "8 warps");
    static_assert(NT % 2 == 0, "NT even");
    constexpr int STAGES = 3;
    constexpr int OFF_BH = 128 * SMSB;
    constexpr int OFF_BL = OFF_BH + BN * SMSB;
    constexpr int BUFSZ  = OFF_BL + BN * SMSB;
    constexpr int BITER  = (BN * 4) / 256;

    extern __shared__ f16 smemf[];
    __shared__ float s_red0[256];
    __shared__ float s_red1[256];

    const int tid  = threadIdx.x;
    const int lane = tid & 31;
    const int wid  = tid >> 5;
    const int warp_m = wid / WARPS_N;
    const int warp_n = wid % WARPS_N;
    const int qr = lane >> 2;
    const int qc = lane & 3;

    const int m0 = blockIdx.y * 128;
    const int n0 = blockIdx.x * BN;

    float acc[MT][NT][4];
#pragma unroll
    for (int i = 0; i < MT; i++)
#pragma unroll
        for (int j = 0; j < NT; j++)
#pragma unroll
            for (int u = 0; u < 4; u++) acc[i][j][u] = 0.f;

    const uint32_t sb = cvta_shared_u32(smemf);

    auto load_chunk = [&](int c, int stg) {
        const int k0 = c << 5;
        const uint32_t base = sb + (uint32_t)stg * (BUFSZ * 2);
#pragma unroll
        for (int i = 0; i < 2; i++) {
            int idx = tid + i * 256;
            int row = idx >> 2, c8 = idx & 3;
            long g = (long)(m0 + row) * lda + k0 + c8 * 8;
            uint32_t so = (uint32_t)(row * SMSB + c8 * 8) * 2;
            cp_async16(base + so, Af + g);
        }
#pragma unroll
        for (int i = 0; i < BITER; i++) {
            int idx = tid + i * 256;
            int row = idx >> 2, c8 = idx & 3;
            long g = (long)(n0 + row) * ldb + k0 + c8 * 8;
            uint32_t so = (uint32_t)(row * SMSB + c8 * 8) * 2;
            cp_async16(base + OFF_BH * 2 + so, Bh + g);
            cp_async16(base + OFF_BL * 2 + so, Bl + g);
        }
    };

    const int nch = K >> 5;
#pragma unroll
    for (int s = 0; s < STAGES - 1; s++) { load_chunk(s, s); cp_commit(); }

    const uint32_t a_off = (uint32_t)(((lane & 15) + warp_m * WM) * SMSB + (lane >> 4) * 8) * 2;
    const uint32_t b_off = (uint32_t)((((lane >> 4) & 1) * 8 + (lane & 7) + warp_n * WN) * SMSB
                                      + ((lane >> 3) & 1) * 8) * 2;

    for (int c = 0; c < nch; c++) {
        const int stg = c % STAGES;
        if (c + STAGES - 1 < nch) {
            load_chunk(c + STAGES - 1, (c + STAGES - 1) % STAGES);
            cp_commit();
            cp_wait<STAGES - 1>();
        } else {
            cp_wait<0>();
        }
        __syncthreads();

        const uint32_t stA  = sb + (uint32_t)stg * (BUFSZ * 2);
        const uint32_t stBh = stA + OFF_BH * 2;
        const uint32_t stBl = stA + OFF_BL * 2;

#pragma unroll
        for (int ks = 0; ks < 2; ks++) {
            const uint32_t kk2 = (uint32_t)ks * 32;
            uint32_t bh[NT][2], bl[NT][2];
#pragma unroll
            for (int in2 = 0; in2 < NT / 2; in2++) {
                uint32_t off = b_off + (uint32_t)in2 * (16 * SMSB * 2) + kk2;
                ldsm_x4(bh[2*in2][0], bh[2*in2][1], bh[2*in2+1][0], bh[2*in2+1][1], stBh + off);
                ldsm_x4(bl[2*in2][0], bl[2*in2][1], bl[2*in2+1][0], bl[2*in2+1][1], stBl + off);
            }
#pragma unroll
            for (int im = 0; im < MT; im++) {
                uint32_t off = a_off + (uint32_t)im * (16 * SMSB * 2) + kk2;
                uint32_t ah[4];
                ldsm_x4(ah[0], ah[1], ah[2], ah[3], stA + off);
#pragma unroll
                for (int in_ = 0; in_ < NT; in_++) {
                    mma_f16(acc[im][in_], ah, bh[in_]);
                    mma_f16(acc[im][in_], ah, bl[in_]);
                }
            }
        }
        __syncthreads();
    }

    // ---- epilogue ----
    float m_in = 0.f, rs_in = 1.f, m_res = 0.f, rs_res = 1.f;
    if (MODE == 1 || MODE == 3) { m_in = instats[0]; rs_in = instats[1]; }
    if (MODE == 0) { m_res = resstats[0]; rs_res = resstats[1]; }

    float lsum = 0.f, lsq = 0.f;
#pragma unroll
    for (int im = 0; im < MT; im++) {
#pragma unroll
        for (int h2 = 0; h2 < 2; h2++) {
            const int row = m0 + warp_m * WM + im * 16 + qr + h2 * 8;
#pragma unroll
            for (int in_ = 0; in_ < NT; in_++) {
                const int col = n0 + warp_n * WN + in_ * 8 + qc * 2;
                float raw0 = acc[im][in_][h2 * 2 + 0] * alpha;
                float raw1 = acc[im][in_][h2 * 2 + 1] * alpha;
                if (MODE == 0) {
                    long si = (long)row * ldc + col;
                    float y0 = __half2float(srch[si])     + __half2float(srcl[si]);
                    float y1 = __half2float(srch[si + 1]) + __half2float(srcl[si + 1]);
                    float v0 = raw0 + bias[col]     + (y0 - m_res) * rs_res;
                    float v1 = raw1 + bias[col + 1] + (y1 - m_res) * rs_res;
                    uint32_t hp, lp;
                    split_f16p(v0, v1, hp, lp);
                    *reinterpret_cast<uint32_t*>(&Cf [(long)row * ldc + col]) = hp;
                    *reinterpret_cast<uint32_t*>(&Cfl[(long)row * ldc + col]) = lp;
                    lsum += v0 + v1;
                    lsq  += v0 * v0 + v1 * v1;
                } else {
                    float v0 = (raw0 - m_in * rowsum[col])     * rs_in + bias[col];
                    float v1 = (raw1 - m_in * rowsum[col + 1]) * rs_in + bias[col + 1];
                    if (MODE == 1) { v0 = fmaxf(v0, 0.f); v1 = fmaxf(v1, 0.f); }
                    *reinterpret_cast<uint32_t*>(&Cf[(long)row * ldc + col]) = pack_f16(v0, v1);
                }
            }
        }
    }

    if (MODE == 0) {
        s_red0[tid] = lsum; s_red1[tid] = lsq;
        __syncthreads();
        for (int s = 128; s > 0; s >>= 1) {
            if (tid < s) { s_red0[tid] += s_red0[tid + s]; s_red1[tid] += s_red1[tid + s]; }
            __syncthreads();
        }
        if (tid == 0) {
            int cta = blockIdx.y * gridDim.x + blockIdx.x;
            psum[cta] = s_red0[0];
            psq [cta] = s_red1[0];
        }
    }
}

// ---------------------------------------------------------------------------
// Flash attention (single-limb K/V; validated R13)
// ---------------------------------------------------------------------------
#define FAS 72

__global__ void __launch_bounds__(256, 2)
flash_attn(const f16* __restrict__ qkvfh, f16* __restrict__ headf, float alpha)
{
    constexpr int QSZ = 64 * FAS;
    constexpr int CSZ = 64 * FAS;

    extern __shared__ f16 fsm[];
    const uint32_t sb = cvta_shared_u32(fsm);
    const uint32_t q_a  = sb;
    const uint32_t ck_a = sb + QSZ * 2;   // 2 bufs x {kh, vh}

    const int tid  = threadIdx.x;
    const int lane = tid & 31;
    const int wid  = tid >> 5;
    const int wrow  = wid & 3;
    const int khalf = wid >> 2;
    const int qr = lane >> 2, qc = lane & 3;
    const long bz = blockIdx.y;
    const long grow0 = bz * SS + blockIdx.x * 64;

#pragma unroll
    for (int i = 0; i < 2; i++) {
        int idx = tid + i * 256;
        int r = idx >> 3, s = idx & 7;
        long g = (grow0 + r) * 192 + s * 8;
        cp_async16(q_a + (uint32_t)(r * FAS + s * 8) * 2, qkvfh + g);
    }
    cp_commit();

    auto load_chunk = [&](int c, int buf) {
        const uint32_t base = ck_a + (uint32_t)buf * 2 * CSZ * 2;
#pragma unroll
        for (int i = 0; i < 2; i++) {
            int idx = tid + i * 256;
            int r = idx >> 3, s = idx & 7;
            long g = (bz * SS + c * 64 + r) * 192 + s * 8;
            uint32_t so = (uint32_t)(r * FAS + s * 8) * 2;
            cp_async16(base + so,           qkvfh + g + 64);
            cp_async16(base + CSZ * 2 + so, qkvfh + g + 128);
        }
        cp_commit();
    };

    load_chunk(0, 0);
    cp_wait<1>();
    __syncthreads();

    const uint32_t qa_off = (uint32_t)((lane & 15) + wrow * 16) * (FAS * 2) + (lane >> 4) * 16;
    uint32_t qa[4][4];
#pragma unroll
    for (int ks = 0; ks < 4; ks++)
        ldsm_x4(qa[ks][0], qa[ks][1], qa[ks][2], qa[ks][3], q_a + qa_off + ks * 32);

    const uint32_t kb_off = (uint32_t)(khalf * 32 + ((lane >> 4) & 1) * 8 + (lane & 7)) * (FAS * 2)
                            + ((lane >> 3) & 1) * 16;
    const uint32_t vb_off = (uint32_t)(khalf * 32 + (lane & 7) + ((lane >> 3) & 1) * 8) * (FAS * 2)
                            + ((lane >> 4) & 1) * 16;

    float o[8][4];
#pragma unroll
    for (int t = 0; t < 8; t++)
#pragma unroll
        for (int u = 0; u < 4; u++) o[t][u] = 0.f;
    float rs0 = 0.f, rs1 = 0.f;

    for (int c = 0; c < SS / 64; c++) {
        const int buf = c & 1;
        cp_wait<0>();
        __syncthreads();
        if (c + 1 < SS / 64) load_chunk(c + 1, buf ^ 1);

        const uint32_t kh_a = ck_a + (uint32_t)buf * 2 * CSZ * 2;
        const uint32_t vh_a = kh_a + CSZ * 2;

        float s[4][4];
#pragma unroll
        for (int j = 0; j < 4; j++)
#pragma unroll
            for (int u = 0; u < 4; u++) s[j][u] = 0.f;

#pragma unroll
        for (int ks = 0; ks < 4; ks++) {
            uint32_t kbh[4][2];
#pragma unroll
            for (int j4 = 0; j4 < 2; j4++) {
                uint32_t off = kb_off + (uint32_t)j4 * (16 * FAS * 2) + ks * 32;
                ldsm_x4(kbh[2*j4][0], kbh[2*j4][1], kbh[2*j4+1][0], kbh[2*j4+1][1], kh_a + off);
            }
#pragma unroll
            for (int j = 0; j < 4; j++)
                mma_f16(s[j], qa[ks], kbh[j]);
        }

        uint32_t pa[2][4];
#pragma unroll
        for (int j = 0; j < 4; j++) {
            float p0 = __expf(s[j][0] * alpha);
            float p1 = __expf(s[j][1] * alpha);
            float p2 = __expf(s[j][2] * alpha);
            float p3 = __expf(s[j][3] * alpha);
            rs0 += p0 + p1;
            rs1 += p2 + p3;
            int ks2 = j >> 1, half = (j & 1) * 2;
            pa[ks2][half + 0] = pack_f16(p0, p1);
            pa[ks2][half + 1] = pack_f16(p2, p3);
        }

#pragma unroll
        for (int ks = 0; ks < 2; ks++) {
            uint32_t vbh[8][2];
#pragma unroll
            for (int i = 0; i < 4; i++) {
                uint32_t off = vb_off + (uint32_t)ks * (16 * FAS * 2) + i * 32;
                ldsm_x4_t(vbh[2*i][0], vbh[2*i][1], vbh[2*i+1][0], vbh[2*i+1][1], vh_a + off);
            }
#pragma unroll
            for (int t = 0; t < 8; t++)
                mma_f16(o[t], pa[ks], vbh[t]);
        }
    }

    rs0 += __shfl_xor_sync(0xffffffffu, rs0, 1);
    rs0 += __shfl_xor_sync(0xffffffffu, rs0, 2);
    rs1 += __shfl_xor_sync(0xffffffffu, rs1, 1);
    rs1 += __shfl_xor_sync(0xffffffffu, rs1, 2);

    __syncthreads();
    float* sof = reinterpret_cast<float*>(fsm + QSZ);
    float4* sof4 = reinterpret_cast<float4*>(sof);
    float* zf = sof + 4 * 8 * 32 * 4;

    if (wid >= 4) {
        int base = (wid - 4) * 256;
#pragma unroll
        for (int t = 0; t < 8; t++) {
            float4 v; v.x = o[t][0]; v.y = o[t][1]; v.z = o[t][2]; v.w = o[t][3];
            sof4[base + t * 32 + lane] = v;
        }
        if (qc == 0) {
            zf[(wid - 4) * 16 + qr]     = rs0;
            zf[(wid - 4) * 16 + qr + 8] = rs1;
        }
    }
    __syncthreads();
    if (wid < 4) {
        int base = wid * 256;
#pragma unroll
        for (int t = 0; t < 8; t++) {
            float4 v = sof4[base + t * 32 + lane];
            o[t][0] += v.x; o[t][1] += v.y; o[t][2] += v.z; o[t][3] += v.w;
        }
        rs0 += zf[wid * 16 + qr];
        rs1 += zf[wid * 16 + qr + 8];
        float inv0 = 1.0f / rs0;
        float inv1 = 1.0f / rs1;
        long g0 = grow0 + wid * 16 + qr;
#pragma unroll
        for (int t = 0; t < 8; t++) {
            int col = t * 8 + qc * 2;
            *reinterpret_cast<uint32_t*>(&headf[g0 * DKK + col]) =
                pack_f16(o[t][0] * inv0, o[t][1] * inv0);
            *reinterpret_cast<uint32_t*>(&headf[(g0 + 8) * DKK + col]) =
                pack_f16(o[t][2] * inv1, o[t][3] * inv1);
        }
    }
}

// ---------------------------------------------------------------------------
// Weight prep
// ---------------------------------------------------------------------------
__device__ __forceinline__ void wsplit(float w, f16& oh, f16& ol) {
    f16 h = __float2half_rn(w);
    oh = __float2half_rn(__half2float(h) * 1024.0f);
    ol = __float2half_rn((w - __half2float(h)) * 1024.0f);
}

__global__ void transpose_split_f16(const float* __restrict__ in,
                                    f16* __restrict__ oh, f16* __restrict__ ol,
                                    int R, int C_) {
    __shared__ float tt[32][33];
    int r0 = blockIdx.y * 32, c0 = blockIdx.x * 32;
#pragma unroll
    for (int i = 0; i < 32; i += 8)
        tt[threadIdx.y + i][threadIdx.x] = in[(long)(r0 + threadIdx.y + i) * C_ + c0 + threadIdx.x];
    __syncthreads();
#pragma unroll
    for (int i = 0; i < 32; i += 8) {
        long o = (long)(c0 + threadIdx.y + i) * R + r0 + threadIdx.x;
        wsplit(tt[threadIdx.x][threadIdx.y + i], oh[o], ol[o]);
    }
}

__global__ void colsum_kernel(const float* __restrict__ W, float* __restrict__ out,
                              int K, int N) {
    int n = blockIdx.x * 256 + threadIdx.x;
    if (n >= N) return;
    float s = 0.f;
    for (int k = 0; k < K; k++) s += W[(long)k * N + n];
    out[n] = s;
}

__global__ void prep_qkvw(const float* __restrict__ Wq, const float* __restrict__ Wk,
                          const float* __restrict__ Wv, const float* __restrict__ bq,
                          const float* __restrict__ bk, const float* __restrict__ bv) {
    int idx = blockIdx.x * 256 + threadIdx.x;
    if (idx < 192 * DD) {
        int n = idx >> 9, k = idx & 511;
        const float* W = (n < 64) ? Wq : ((n < 128) ? Wk : Wv);
        float v = W[k * DKK + (n & 63)];
        wsplit(v, g_wqkvfh[idx], g_wqkvfl[idx]);
    }
    if (idx < 192) {
        g_bqkv[idx] = (idx < 64) ? bq[idx] : ((idx < 128) ? bk[idx - 64] : bv[idx - 128]);
        const float* W = (idx < 64) ? Wq : ((idx < 128) ? Wk : Wv);
        float s = 0.f;
        for (int k = 0; k < DD; k++) s += W[k * DKK + (idx & 63)];
        g_rsqkv[idx] = s;
    }
}

__global__ void prep_wo(const float* __restrict__ Wo) {
    int idx = blockIdx.x * 256 + threadIdx.x;
    if (idx >= DD * DKK) return;
    int e = idx / DKK, t = idx % DKK;
    float s = 0.f;
#pragma unroll
    for (int j = 0; j < 8; j++) s += Wo[(j * DKK + t) * DD + e];
    wsplit(s, g_wofh[idx], g_wofl[idx]);
}

// ---------------------------------------------------------------------------
// Embedding + positional encoding -> y2 pair; seeds identity stats
// ---------------------------------------------------------------------------
__global__ void embed_kernel(const int* __restrict__ ids, const float* __restrict__ emb) {
    long i2 = (long)blockIdx.x * 256 + threadIdx.x;
    if (blockIdx.x == 0 && threadIdx.x == 0) {
        g_statsB[0] = 0.0f;
        g_statsB[1] = 1.0f;
    }
    if (i2 >= NTOT / 2) return;
    long e = i2 * 2;
    int d  = (int)(e & (DD - 1));
    int bs = (int)(e >> 9);
    int s  = bs & (SS - 1);
    int id = ids[bs];
    float v0 = 0.f, v1 = 0.f;
    if (id != 0) {
        const float* er = emb + (long)id * DD;
        v0 = er[d]; v1 = er[d + 1];
    }
    double f0 = pow(10000.0, (double)d / 256.0);
    double f1 = pow(10000.0, (double)(d + 1) / 256.0);
    v0 += sinf((float)((double)s / f0));
    v1 += cosf((float)((double)s / f1));
    uint32_t hp, lp;
    split_f16p(v0, v1, hp, lp);
    *reinterpret_cast<uint32_t*>(&g_xfh[e]) = hp;
    *reinterpret_cast<uint32_t*>(&g_xfl[e]) = lp;
}

// ---------------------------------------------------------------------------
// LayerNorm finalize: partials -> (m, rs)
// ---------------------------------------------------------------------------
__global__ void finalize_kernel(int n, float* __restrict__ stats_out) {
    __shared__ double ds[256], dq[256];
    double a = 0.0, b = 0.0;
    for (int i = threadIdx.x; i < n; i += 256) {
        a += (double)g_psum[i];
        b += (double)g_psq[i];
    }
    ds[threadIdx.x] = a; dq[threadIdx.x] = b; __syncthreads();
    for (int s = 128; s > 0; s >>= 1) {
        if (threadIdx.x < s) {
            ds[threadIdx.x] += ds[threadIdx.x + s];
            dq[threadIdx.x] += dq[threadIdx.x + s];
        }
        __syncthreads();
    }
    if (threadIdx.x == 0) {
        double m = ds[0] / (double)NTOT;
        double v = dq[0] / (double)NTOT - m * m;
        stats_out[0] = (float)m;
        stats_out[1] = (float)(1.0 / sqrt(v + 1e-5));
    }
}

// final output: out = (yh + yl - m) * rs  (fp32)
__global__ void normalize_out(const f16* __restrict__ yh, const f16* __restrict__ yl,
                              const float* __restrict__ stats, float* __restrict__ out) {
    long i2 = (long)blockIdx.x * 256 + threadIdx.x;
    long e = i2 * 2;
    if (e >= NTOT) return;
    float m = stats[0], rs = stats[1];
    float y0 = __half2float(yh[e])     + __half2float(yl[e]);
    float y1 = __half2float(yh[e + 1]) + __half2float(yl[e + 1]);
    float2 o; o.x = (y0 - m) * rs; o.y = (y1 - m) * rs;
    *reinterpret_cast<float2*>(&out[e]) = o;
}

// ---------------------------------------------------------------------------
// Launch
// ---------------------------------------------------------------------------
extern "C" void kernel_launch(void* const* d_in, const int* in_sizes, int n_in,
                              void* d_out, int out_size)
{
    const int*   ids = (const int*)  d_in[0];
    const float* emb = (const float*)d_in[1];
    const float* Wq  = (const float*)d_in[2];
    const float* bq  = (const float*)d_in[3];
    const float* Wk  = (const float*)d_in[4];
    const float* bk  = (const float*)d_in[5];
    const float* Wv  = (const float*)d_in[6];
    const float* bv  = (const float*)d_in[7];
    const float* Wo  = (const float*)d_in[8];
    const float* bo  = (const float*)d_in[9];
    const float* W1  = (const float*)d_in[10];
    const float* b1  = (const float*)d_in[11];
    const float* W2  = (const float*)d_in[12];
    const float* b2  = (const float*)d_in[13];

    float *bqkv, *rsqkv, *rsw1, *psum, *psq, *statsA, *statsB;
    f16 *xfh, *xfl, *x1fh, *x1fl, *qkvfh, *headf, *hf;
    f16 *wqkvfh, *wqkvfl, *wofh, *wofl, *w1fh, *w1fl, *w2fh, *w2fl;
    cudaGetSymbolAddress((void**)&xfh,    g_xfh);
    cudaGetSymbolAddress((void**)&xfl,    g_xfl);
    cudaGetSymbolAddress((void**)&x1fh,   g_x1fh);
    cudaGetSymbolAddress((void**)&x1fl,   g_x1fl);
    cudaGetSymbolAddress((void**)&qkvfh,  g_qkvfh);
    cudaGetSymbolAddress((void**)&headf,  g_headf);
    cudaGetSymbolAddress((void**)&hf,     g_hf);
    cudaGetSymbolAddress((void**)&wqkvfh, g_wqkvfh);
    cudaGetSymbolAddress((void**)&wqkvfl, g_wqkvfl);
    cudaGetSymbolAddress((void**)&wofh,   g_wofh);
    cudaGetSymbolAddress((void**)&wofl,   g_wofl);
    cudaGetSymbolAddress((void**)&w1fh,   g_w1fh);
    cudaGetSymbolAddress((void**)&w1fl,   g_w1fl);
    cudaGetSymbolAddress((void**)&w2fh,   g_w2fh);
    cudaGetSymbolAddress((void**)&w2fl,   g_w2fl);
    cudaGetSymbolAddress((void**)&bqkv,   g_bqkv);
    cudaGetSymbolAddress((void**)&rsqkv,  g_rsqkv);
    cudaGetSymbolAddress((void**)&rsw1,   g_rsw1);
    cudaGetSymbolAddress((void**)&psum,   g_psum);
    cudaGetSymbolAddress((void**)&psq,    g_psq);
    cudaGetSymbolAddress((void**)&statsA, g_statsA);
    cudaGetSymbolAddress((void**)&statsB, g_statsB);

    const int SM128 = 3 * (128 + 256) * SMSB * 2;    // 92160
    const int SM64  = 3 * (128 + 128) * SMSB * 2;    // 61440
    const int SMFA  = (64 * FAS + 4 * 64 * FAS) * 2; // 46080

    cudaFuncSetAttribute((const void*)gemm2<64, 32, 32, 3>,
                         cudaFuncAttributeMaxDynamicSharedMemorySize, SM64);
    cudaFuncSetAttribute((const void*)gemm2<128, 64, 32, 0>,
                         cudaFuncAttributeMaxDynamicSharedMemorySize, SM128);
    cudaFuncSetAttribute((const void*)gemm2<128, 64, 32, 1>,
                         cudaFuncAttributeMaxDynamicSharedMemorySize, SM128);
    cudaFuncSetAttribute((const void*)flash_attn,
                         cudaFuncAttributeMaxDynamicSharedMemorySize, SMFA);

    const float inv_div = 1.0f / 32.0f;
    const float inv_ws  = 1.0f / 1024.0f;
    dim3 tb(32, 8);

    // ---- weight prep ----
    prep_qkvw<<<(192 * DD + 255) / 256, 256>>>(Wq, Wk, Wv, bq, bk, bv);
    prep_wo<<<(DD * DKK + 255) / 256, 256>>>(Wo);
    transpose_split_f16<<<dim3(DFFN / 32, DD / 32), tb>>>(W1, w1fh, w1fl, DD, DFFN);
    transpose_split_f16<<<dim3(DD / 32, DFFN / 32), tb>>>(W2, w2fh, w2fl, DFFN, DD);
    colsum_kernel<<<DFFN / 256, 256>>>(W1, rsw1, DD, DFFN);

    embed_kernel<<<NTOT / 512, 256>>>(ids, emb);

    for (int it = 0; it < NREP; it++) {
        // QKV (norm_B folded): single-limb output (flash only reads hi)
        gemm2<64, 32, 32, 3><<<dim3(3, 128, 1), 256, SM64>>>(
            xfh, DD, wqkvfh, wqkvfl, DD, bqkv, statsB, rsqkv,
            0, 0, 0, qkvfh, 0, 192, DD, inv_ws, 0, 0);

        // flash attention (single-limb K/V)
        flash_attn<<<dim3(SS / 64, BB), 256, SMFA>>>(qkvfh, headf, inv_div);

        // y1 = head @ Wo_eff + bo + norm_B(y2-pair), pair out + LN partials
        gemm2<128, 64, 32, 0><<<dim3(4, 128, 1), 256, SM128>>>(
            headf, DKK, wofh, wofl, DKK, bo, 0, 0,
            xfh, xfl, statsB, x1fh, x1fl, DD, DKK, inv_ws, psum, psq);

        finalize_kernel<<<1, 256>>>(512, statsA);

        // h = relu(norm_A(y1) @ W1 + b1) (input-norm folded)
        gemm2<128, 64, 32, 1><<<dim3(16, 128, 1), 256, SM128>>>(
            x1fh, DD, w1fh, w1fl, DD, b1, statsA, rsw1,
            0, 0, 0, hf, 0, DFFN, DD, inv_ws, 0, 0);

        // y2 = h @ W2 + b2 + norm_A(y1-pair), pair out + LN partials
        gemm2<128, 64, 32, 0><<<dim3(4, 128, 1), 256, SM128>>>(
            hf, DFFN, w2fh, w2fl, DFFN, b2, 0, 0,
            x1fh, x1fl, statsA, xfh, xfl, DD, DFFN, inv_ws, psum, psq);

        finalize_kernel<<<1, 256>>>(512, statsB);
    }

    normalize_out<<<NTOT / 512, 256>>>(xfh, xfl, statsB, (float*)d_out);
}

// round 16
// speedup vs baseline: 1.2882x; 1.2655x over previous
#include <cuda_runtime.h>
#include <cuda_fp16.h>
#include <math.h>
#include <stdint.h>

#define BB   8
#define SS   2048
#define DD   512
#define DKK  64
#define DFFN 2048
#define NREP 6
#define MSROWS (BB*SS)          // 16384
#define NTOT (BB*SS*DD)         // 8388608

typedef __half f16;

// ---------------------------------------------------------------------------
// Scratch
// ---------------------------------------------------------------------------
__device__ f16 g_xfh [NTOT];    // y2 pair (post-FFN stream / embed at it 0)
__device__ f16 g_xfl [NTOT];
__device__ f16 g_x1fh[NTOT];    // y1 pair (post-attention stream)
__device__ f16 g_x1fl[NTOT];
__device__ f16 g_qkvfh[MSROWS*192];
__device__ f16 g_headf[MSROWS*DKK];
__device__ f16 g_hf[(long)MSROWS*DFFN];

__device__ f16 g_wqkvfh[192*DD];
__device__ f16 g_wqkvfl[192*DD];
__device__ f16 g_wofh[DD*DKK];
__device__ f16 g_wofl[DD*DKK];
__device__ f16 g_w1f[DFFN*DD];      // single-limb fp16 (unscaled)
__device__ f16 g_w2f[DD*DFFN];      // single-limb fp16 (unscaled)
__device__ float g_bqkv[192];
__device__ float g_rsqkv[192];      // per-output-col sum of combined QKV weight
__device__ float g_rsw1[DFFN];      // colsum of W1

__device__ float g_psum[1024];
__device__ float g_psq [1024];
__device__ float g_statsA[2];       // mid-LN (m, rs)
__device__ float g_statsB[2];       // post-LN (m, rs); seeded {0,1} by embed

// ---------------------------------------------------------------------------
// Helpers
// ---------------------------------------------------------------------------
__device__ __forceinline__ uint32_t cvta_shared_u32(const void* p) {
    uint32_t a;
    asm("{ .reg .u64 t; cvta.to.shared.u64 t, %1; cvt.u32.u64 %0, t; }" : "=r"(a) : "l"(p));
    return a;
}
__device__ __forceinline__ void cp_async16(uint32_t saddr, const void* gptr) {
    asm volatile("cp.async.cg.shared.global [%0], [%1], 16;" :: "r"(saddr), "l"(gptr));
}
__device__ __forceinline__ void cp_commit() {
    asm volatile("cp.async.commit_group;" ::: "memory");
}
template<int N>
__device__ __forceinline__ void cp_wait() {
    asm volatile("cp.async.wait_group %0;" :: "n"(N) : "memory");
}
__device__ __forceinline__ void ldsm_x4(uint32_t& r0, uint32_t& r1, uint32_t& r2, uint32_t& r3,
                                        uint32_t addr) {
    asm volatile("ldmatrix.sync.aligned.m8n8.x4.shared.b16 {%0,%1,%2,%3}, [%4];"
                 : "=r"(r0), "=r"(r1), "=r"(r2), "=r"(r3) : "r"(addr));
}
__device__ __forceinline__ void ldsm_x4_t(uint32_t& r0, uint32_t& r1, uint32_t& r2, uint32_t& r3,
                                          uint32_t addr) {
    asm volatile("ldmatrix.sync.aligned.m8n8.x4.trans.shared.b16 {%0,%1,%2,%3}, [%4];"
                 : "=r"(r0), "=r"(r1), "=r"(r2), "=r"(r3) : "r"(addr));
}
__device__ __forceinline__ uint32_t pack_f16(float e0, float e1) {
    uint32_t r;
    asm("cvt.rn.f16x2.f32 %0, %1, %2;" : "=r"(r) : "f"(e1), "f"(e0));
    return r;
}
__device__ __forceinline__ void split_f16p(float e0, float e1, uint32_t& hi, uint32_t& lo) {
    f16 h0 = __float2half_rn(e0);
    f16 h1 = __float2half_rn(e1);
    float l0 = e0 - __half2float(h0);
    float l1 = e1 - __half2float(h1);
    hi = ((uint32_t)__half_as_ushort(h1) << 16) | __half_as_ushort(h0);
    lo = pack_f16(l0, l1);
}
__device__ __forceinline__ void mma_f16(float* c, const uint32_t* a, const uint32_t* b) {
    asm volatile(
        "mma.sync.aligned.m16n8k16.row.col.f32.f16.f16.f32 "
        "{%0,%1,%2,%3}, {%4,%5,%6,%7}, {%8,%9}, {%0,%1,%2,%3};"
        : "+f"(c[0]), "+f"(c[1]), "+f"(c[2]), "+f"(c[3])
        : "r"(a[0]), "r"(a[1]), "r"(a[2]), "r"(a[3]), "r"(b[0]), "r"(b[1]));
}

#define SMSB 40

// ---------------------------------------------------------------------------
// Unified fp16 GEMM with LN folding. B2: weight has lo limb (2-term) or not.
// MODE 0: v = raw + bias + (src pair - m_res)*rs_res -> pair out + LN partials
// MODE 1: v = (raw - m_in*rowsum[col])*rs_in + bias, ReLU -> single out
// MODE 3: v = (raw - m_in*rowsum[col])*rs_in + bias -> single out (no ReLU)
// ---------------------------------------------------------------------------
template<int BN, int WM, int WN, int MODE, bool B2>
__global__ void __launch_bounds__(256, 2)
gemm2(const f16* __restrict__ Af, int lda,
      const f16* __restrict__ Bh, const f16* __restrict__ Bl, int ldb,
      const float* __restrict__ bias,
      const float* __restrict__ instats, const float* __restrict__ rowsum,
      const f16* __restrict__ srch, const f16* __restrict__ srcl,
      const float* __restrict__ resstats,
      f16* __restrict__ Cf, f16* __restrict__ Cfl,
      int ldc, int K, float alpha,
      float* __restrict__ psum, float* __restrict__ psq)
{
    constexpr int MT = WM / 16;
    constexpr int NT = WN / 8;
    constexpr int WARPS_N = BN / WN;
    static_assert((128 / WM) * (BN / WN) == 8, "8 warps");
    static_assert(NT % 2 == 0, "NT even");
    constexpr int STAGES = 3;
    constexpr int OFF_BH = 128 * SMSB;
    constexpr int OFF_BL = OFF_BH + BN * SMSB;
    constexpr int BUFSZ  = OFF_BL + (B2 ? BN * SMSB : 0);
    constexpr int BITER  = (BN * 4) / 256;

    extern __shared__ f16 smemf[];
    __shared__ float s_red0[256];
    __shared__ float s_red1[256];

    const int tid  = threadIdx.x;
    const int lane = tid & 31;
    const int wid  = tid >> 5;
    const int warp_m = wid / WARPS_N;
    const int warp_n = wid % WARPS_N;
    const int qr = lane >> 2;
    const int qc = lane & 3;

    const int m0 = blockIdx.y * 128;
    const int n0 = blockIdx.x * BN;

    float acc[MT][NT][4];
#pragma unroll
    for (int i = 0; i < MT; i++)
#pragma unroll
        for (int j = 0; j < NT; j++)
#pragma unroll
            for (int u = 0; u < 4; u++) acc[i][j][u] = 0.f;

    const uint32_t sb = cvta_shared_u32(smemf);

    auto load_chunk = [&](int c, int stg) {
        const int k0 = c << 5;
        const uint32_t base = sb + (uint32_t)stg * (BUFSZ * 2);
#pragma unroll
        for (int i = 0; i < 2; i++) {
            int idx = tid + i * 256;
            int row = idx >> 2, c8 = idx & 3;
            long g = (long)(m0 + row) * lda + k0 + c8 * 8;
            uint32_t so = (uint32_t)(row * SMSB + c8 * 8) * 2;
            cp_async16(base + so, Af + g);
        }
#pragma unroll
        for (int i = 0; i < BITER; i++) {
            int idx = tid + i * 256;
            int row = idx >> 2, c8 = idx & 3;
            long g = (long)(n0 + row) * ldb + k0 + c8 * 8;
            uint32_t so = (uint32_t)(row * SMSB + c8 * 8) * 2;
            cp_async16(base + OFF_BH * 2 + so, Bh + g);
            if (B2) cp_async16(base + OFF_BL * 2 + so, Bl + g);
        }
    };

    const int nch = K >> 5;
#pragma unroll
    for (int s = 0; s < STAGES - 1; s++) { load_chunk(s, s); cp_commit(); }

    const uint32_t a_off = (uint32_t)(((lane & 15) + warp_m * WM) * SMSB + (lane >> 4) * 8) * 2;
    const uint32_t b_off = (uint32_t)((((lane >> 4) & 1) * 8 + (lane & 7) + warp_n * WN) * SMSB
                                      + ((lane >> 3) & 1) * 8) * 2;

    for (int c = 0; c < nch; c++) {
        const int stg = c % STAGES;
        if (c + STAGES - 1 < nch) {
            load_chunk(c + STAGES - 1, (c + STAGES - 1) % STAGES);
            cp_commit();
            cp_wait<STAGES - 1>();
        } else {
            cp_wait<0>();
        }
        __syncthreads();

        const uint32_t stA  = sb + (uint32_t)stg * (BUFSZ * 2);
        const uint32_t stBh = stA + OFF_BH * 2;
        const uint32_t stBl = stA + OFF_BL * 2;

#pragma unroll
        for (int ks = 0; ks < 2; ks++) {
            const uint32_t kk2 = (uint32_t)ks * 32;
            uint32_t bh[NT][2], bl[NT][2];
#pragma unroll
            for (int in2 = 0; in2 < NT / 2; in2++) {
                uint32_t off = b_off + (uint32_t)in2 * (16 * SMSB * 2) + kk2;
                ldsm_x4(bh[2*in2][0], bh[2*in2][1], bh[2*in2+1][0], bh[2*in2+1][1], stBh + off);
                if (B2)
                    ldsm_x4(bl[2*in2][0], bl[2*in2][1], bl[2*in2+1][0], bl[2*in2+1][1], stBl + off);
            }
#pragma unroll
            for (int im = 0; im < MT; im++) {
                uint32_t off = a_off + (uint32_t)im * (16 * SMSB * 2) + kk2;
                uint32_t ah[4];
                ldsm_x4(ah[0], ah[1], ah[2], ah[3], stA + off);
#pragma unroll
                for (int in_ = 0; in_ < NT; in_++) {
                    mma_f16(acc[im][in_], ah, bh[in_]);
                    if (B2) mma_f16(acc[im][in_], ah, bl[in_]);
                }
            }
        }
        __syncthreads();
    }

    // ---- epilogue ----
    float m_in = 0.f, rs_in = 1.f, m_res = 0.f, rs_res = 1.f;
    if (MODE == 1 || MODE == 3) { m_in = instats[0]; rs_in = instats[1]; }
    if (MODE == 0) { m_res = resstats[0]; rs_res = resstats[1]; }

    float lsum = 0.f, lsq = 0.f;
#pragma unroll
    for (int im = 0; im < MT; im++) {
#pragma unroll
        for (int h2 = 0; h2 < 2; h2++) {
            const int row = m0 + warp_m * WM + im * 16 + qr + h2 * 8;
#pragma unroll
            for (int in_ = 0; in_ < NT; in_++) {
                const int col = n0 + warp_n * WN + in_ * 8 + qc * 2;
                float raw0 = acc[im][in_][h2 * 2 + 0] * alpha;
                float raw1 = acc[im][in_][h2 * 2 + 1] * alpha;
                if (MODE == 0) {
                    long si = (long)row * ldc + col;
                    float y0 = __half2float(srch[si])     + __half2float(srcl[si]);
                    float y1 = __half2float(srch[si + 1]) + __half2float(srcl[si + 1]);
                    float v0 = raw0 + bias[col]     + (y0 - m_res) * rs_res;
                    float v1 = raw1 + bias[col + 1] + (y1 - m_res) * rs_res;
                    uint32_t hp, lp;
                    split_f16p(v0, v1, hp, lp);
                    *reinterpret_cast<uint32_t*>(&Cf [(long)row * ldc + col]) = hp;
                    *reinterpret_cast<uint32_t*>(&Cfl[(long)row * ldc + col]) = lp;
                    lsum += v0 + v1;
                    lsq  += v0 * v0 + v1 * v1;
                } else {
                    float v0 = (raw0 - m_in * rowsum[col])     * rs_in + bias[col];
                    float v1 = (raw1 - m_in * rowsum[col + 1]) * rs_in + bias[col + 1];
                    if (MODE == 1) { v0 = fmaxf(v0, 0.f); v1 = fmaxf(v1, 0.f); }
                    *reinterpret_cast<uint32_t*>(&Cf[(long)row * ldc + col]) = pack_f16(v0, v1);
                }
            }
        }
    }

    if (MODE == 0) {
        s_red0[tid] = lsum; s_red1[tid] = lsq;
        __syncthreads();
        for (int s = 128; s > 0; s >>= 1) {
            if (tid < s) { s_red0[tid] += s_red0[tid + s]; s_red1[tid] += s_red1[tid + s]; }
            __syncthreads();
        }
        if (tid == 0) {
            int cta = blockIdx.y * gridDim.x + blockIdx.x;
            psum[cta] = s_red0[0];
            psq [cta] = s_red1[0];
        }
    }
}

// ---------------------------------------------------------------------------
// Flash attention (single-limb K/V; validated R13)
// ---------------------------------------------------------------------------
#define FAS 72

__global__ void __launch_bounds__(256, 2)
flash_attn(const f16* __restrict__ qkvfh, f16* __restrict__ headf, float alpha)
{
    constexpr int QSZ = 64 * FAS;
    constexpr int CSZ = 64 * FAS;

    extern __shared__ f16 fsm[];
    const uint32_t sb = cvta_shared_u32(fsm);
    const uint32_t q_a  = sb;
    const uint32_t ck_a = sb + QSZ * 2;   // 2 bufs x {kh, vh}

    const int tid  = threadIdx.x;
    const int lane = tid & 31;
    const int wid  = tid >> 5;
    const int wrow  = wid & 3;
    const int khalf = wid >> 2;
    const int qr = lane >> 2, qc = lane & 3;
    const long bz = blockIdx.y;
    const long grow0 = bz * SS + blockIdx.x * 64;

#pragma unroll
    for (int i = 0; i < 2; i++) {
        int idx = tid + i * 256;
        int r = idx >> 3, s = idx & 7;
        long g = (grow0 + r) * 192 + s * 8;
        cp_async16(q_a + (uint32_t)(r * FAS + s * 8) * 2, qkvfh + g);
    }
    cp_commit();

    auto load_chunk = [&](int c, int buf) {
        const uint32_t base = ck_a + (uint32_t)buf * 2 * CSZ * 2;
#pragma unroll
        for (int i = 0; i < 2; i++) {
            int idx = tid + i * 256;
            int r = idx >> 3, s = idx & 7;
            long g = (bz * SS + c * 64 + r) * 192 + s * 8;
            uint32_t so = (uint32_t)(r * FAS + s * 8) * 2;
            cp_async16(base + so,           qkvfh + g + 64);
            cp_async16(base + CSZ * 2 + so, qkvfh + g + 128);
        }
        cp_commit();
    };

    load_chunk(0, 0);
    cp_wait<1>();
    __syncthreads();

    const uint32_t qa_off = (uint32_t)((lane & 15) + wrow * 16) * (FAS * 2) + (lane >> 4) * 16;
    uint32_t qa[4][4];
#pragma unroll
    for (int ks = 0; ks < 4; ks++)
        ldsm_x4(qa[ks][0], qa[ks][1], qa[ks][2], qa[ks][3], q_a + qa_off + ks * 32);

    const uint32_t kb_off = (uint32_t)(khalf * 32 + ((lane >> 4) & 1) * 8 + (lane & 7)) * (FAS * 2)
                            + ((lane >> 3) & 1) * 16;
    const uint32_t vb_off = (uint32_t)(khalf * 32 + (lane & 7) + ((lane >> 3) & 1) * 8) * (FAS * 2)
                            + ((lane >> 4) & 1) * 16;

    float o[8][4];
#pragma unroll
    for (int t = 0; t < 8; t++)
#pragma unroll
        for (int u = 0; u < 4; u++) o[t][u] = 0.f;
    float rs0 = 0.f, rs1 = 0.f;

    for (int c = 0; c < SS / 64; c++) {
        const int buf = c & 1;
        cp_wait<0>();
        __syncthreads();
        if (c + 1 < SS / 64) load_chunk(c + 1, buf ^ 1);

        const uint32_t kh_a = ck_a + (uint32_t)buf * 2 * CSZ * 2;
        const uint32_t vh_a = kh_a + CSZ * 2;

        float s[4][4];
#pragma unroll
        for (int j = 0; j < 4; j++)
#pragma unroll
            for (int u = 0; u < 4; u++) s[j][u] = 0.f;

#pragma unroll
        for (int ks = 0; ks < 4; ks++) {
            uint32_t kbh[4][2];
#pragma unroll
            for (int j4 = 0; j4 < 2; j4++) {
                uint32_t off = kb_off + (uint32_t)j4 * (16 * FAS * 2) + ks * 32;
                ldsm_x4(kbh[2*j4][0], kbh[2*j4][1], kbh[2*j4+1][0], kbh[2*j4+1][1], kh_a + off);
            }
#pragma unroll
            for (int j = 0; j < 4; j++)
                mma_f16(s[j], qa[ks], kbh[j]);
        }

        uint32_t pa[2][4];
#pragma unroll
        for (int j = 0; j < 4; j++) {
            float p0 = __expf(s[j][0] * alpha);
            float p1 = __expf(s[j][1] * alpha);
            float p2 = __expf(s[j][2] * alpha);
            float p3 = __expf(s[j][3] * alpha);
            rs0 += p0 + p1;
            rs1 += p2 + p3;
            int ks2 = j >> 1, half = (j & 1) * 2;
            pa[ks2][half + 0] = pack_f16(p0, p1);
            pa[ks2][half + 1] = pack_f16(p2, p3);
        }

#pragma unroll
        for (int ks = 0; ks < 2; ks++) {
            uint32_t vbh[8][2];
#pragma unroll
            for (int i = 0; i < 4; i++) {
                uint32_t off = vb_off + (uint32_t)ks * (16 * FAS * 2) + i * 32;
                ldsm_x4_t(vbh[2*i][0], vbh[2*i][1], vbh[2*i+1][0], vbh[2*i+1][1], vh_a + off);
            }
#pragma unroll
            for (int t = 0; t < 8; t++)
                mma_f16(o[t], pa[ks], vbh[t]);
        }
    }

    rs0 += __shfl_xor_sync(0xffffffffu, rs0, 1);
    rs0 += __shfl_xor_sync(0xffffffffu, rs0, 2);
    rs1 += __shfl_xor_sync(0xffffffffu, rs1, 1);
    rs1 += __shfl_xor_sync(0xffffffffu, rs1, 2);

    __syncthreads();
    float* sof = reinterpret_cast<float*>(fsm + QSZ);
    float4* sof4 = reinterpret_cast<float4*>(sof);
    float* zf = sof + 4 * 8 * 32 * 4;

    if (wid >= 4) {
        int base = (wid - 4) * 256;
#pragma unroll
        for (int t = 0; t < 8; t++) {
            float4 v; v.x = o[t][0]; v.y = o[t][1]; v.z = o[t][2]; v.w = o[t][3];
            sof4[base + t * 32 + lane] = v;
        }
        if (qc == 0) {
            zf[(wid - 4) * 16 + qr]     = rs0;
            zf[(wid - 4) * 16 + qr + 8] = rs1;
        }
    }
    __syncthreads();
    if (wid < 4) {
        int base = wid * 256;
#pragma unroll
        for (int t = 0; t < 8; t++) {
            float4 v = sof4[base + t * 32 + lane];
            o[t][0] += v.x; o[t][1] += v.y; o[t][2] += v.z; o[t][3] += v.w;
        }
        rs0 += zf[wid * 16 + qr];
        rs1 += zf[wid * 16 + qr + 8];
        float inv0 = 1.0f / rs0;
        float inv1 = 1.0f / rs1;
        long g0 = grow0 + wid * 16 + qr;
#pragma unroll
        for (int t = 0; t < 8; t++) {
            int col = t * 8 + qc * 2;
            *reinterpret_cast<uint32_t*>(&headf[g0 * DKK + col]) =
                pack_f16(o[t][0] * inv0, o[t][1] * inv0);
            *reinterpret_cast<uint32_t*>(&headf[(g0 + 8) * DKK + col]) =
                pack_f16(o[t][2] * inv1, o[t][3] * inv1);
        }
    }
}

// ---------------------------------------------------------------------------
// Weight prep
// ---------------------------------------------------------------------------
__device__ __forceinline__ void wsplit(float w, f16& oh, f16& ol) {
    f16 h = __float2half_rn(w);
    oh = __float2half_rn(__half2float(h) * 1024.0f);
    ol = __float2half_rn((w - __half2float(h)) * 1024.0f);
}

// transpose + plain fp16 convert (single limb)
__global__ void transpose_f16c(const float* __restrict__ in, f16* __restrict__ o,
                               int R, int C_) {
    __shared__ float tt[32][33];
    int r0 = blockIdx.y * 32, c0 = blockIdx.x * 32;
#pragma unroll
    for (int i = 0; i < 32; i += 8)
        tt[threadIdx.y + i][threadIdx.x] = in[(long)(r0 + threadIdx.y + i) * C_ + c0 + threadIdx.x];
    __syncthreads();
#pragma unroll
    for (int i = 0; i < 32; i += 8) {
        long oi = (long)(c0 + threadIdx.y + i) * R + r0 + threadIdx.x;
        o[oi] = __float2half_rn(tt[threadIdx.x][threadIdx.y + i]);
    }
}

__global__ void colsum_kernel(const float* __restrict__ W, float* __restrict__ out,
                              int K, int N) {
    int n = blockIdx.x * 256 + threadIdx.x;
    if (n >= N) return;
    float s = 0.f;
    for (int k = 0; k < K; k++) s += W[(long)k * N + n];
    out[n] = s;
}

__global__ void prep_qkvw(const float* __restrict__ Wq, const float* __restrict__ Wk,
                          const float* __restrict__ Wv, const float* __restrict__ bq,
                          const float* __restrict__ bk, const float* __restrict__ bv) {
    int idx = blockIdx.x * 256 + threadIdx.x;
    if (idx < 192 * DD) {
        int n = idx >> 9, k = idx & 511;
        const float* W = (n < 64) ? Wq : ((n < 128) ? Wk : Wv);
        float v = W[k * DKK + (n & 63)];
        wsplit(v, g_wqkvfh[idx], g_wqkvfl[idx]);
    }
    if (idx < 192) {
        g_bqkv[idx] = (idx < 64) ? bq[idx] : ((idx < 128) ? bk[idx - 64] : bv[idx - 128]);
        const float* W = (idx < 64) ? Wq : ((idx < 128) ? Wk : Wv);
        float s = 0.f;
        for (int k = 0; k < DD; k++) s += W[k * DKK + (idx & 63)];
        g_rsqkv[idx] = s;
    }
}

__global__ void prep_wo(const float* __restrict__ Wo) {
    int idx = blockIdx.x * 256 + threadIdx.x;
    if (idx >= DD * DKK) return;
    int e = idx / DKK, t = idx % DKK;
    float s = 0.f;
#pragma unroll
    for (int j = 0; j < 8; j++) s += Wo[(j * DKK + t) * DD + e];
    wsplit(s, g_wofh[idx], g_wofl[idx]);
}

// ---------------------------------------------------------------------------
// Embedding + positional encoding -> y2 pair; seeds identity stats
// ---------------------------------------------------------------------------
__global__ void embed_kernel(const int* __restrict__ ids, const float* __restrict__ emb) {
    long i2 = (long)blockIdx.x * 256 + threadIdx.x;
    if (blockIdx.x == 0 && threadIdx.x == 0) {
        g_statsB[0] = 0.0f;
        g_statsB[1] = 1.0f;
    }
    if (i2 >= NTOT / 2) return;
    long e = i2 * 2;
    int d  = (int)(e & (DD - 1));
    int bs = (int)(e >> 9);
    int s  = bs & (SS - 1);
    int id = ids[bs];
    float v0 = 0.f, v1 = 0.f;
    if (id != 0) {
        const float* er = emb + (long)id * DD;
        v0 = er[d]; v1 = er[d + 1];
    }
    double f0 = pow(10000.0, (double)d / 256.0);
    double f1 = pow(10000.0, (double)(d + 1) / 256.0);
    v0 += sinf((float)((double)s / f0));
    v1 += cosf((float)((double)s / f1));
    uint32_t hp, lp;
    split_f16p(v0, v1, hp, lp);
    *reinterpret_cast<uint32_t*>(&g_xfh[e]) = hp;
    *reinterpret_cast<uint32_t*>(&g_xfl[e]) = lp;
}

// ---------------------------------------------------------------------------
// LayerNorm finalize: partials -> (m, rs)
// ---------------------------------------------------------------------------
__global__ void finalize_kernel(int n, float* __restrict__ stats_out) {
    __shared__ double ds[256], dq[256];
    double a = 0.0, b = 0.0;
    for (int i = threadIdx.x; i < n; i += 256) {
        a += (double)g_psum[i];
        b += (double)g_psq[i];
    }
    ds[threadIdx.x] = a; dq[threadIdx.x] = b; __syncthreads();
    for (int s = 128; s > 0; s >>= 1) {
        if (threadIdx.x < s) {
            ds[threadIdx.x] += ds[threadIdx.x + s];
            dq[threadIdx.x] += dq[threadIdx.x + s];
        }
        __syncthreads();
    }
    if (threadIdx.x == 0) {
        double m = ds[0] / (double)NTOT;
        double v = dq[0] / (double)NTOT - m * m;
        stats_out[0] = (float)m;
        stats_out[1] = (float)(1.0 / sqrt(v + 1e-5));
    }
}

// final output: out = (yh + yl - m) * rs  (fp32)
__global__ void normalize_out(const f16* __restrict__ yh, const f16* __restrict__ yl,
                              const float* __restrict__ stats, float* __restrict__ out) {
    long i2 = (long)blockIdx.x * 256 + threadIdx.x;
    long e = i2 * 2;
    if (e >= NTOT) return;
    float m = stats[0], rs = stats[1];
    float y0 = __half2float(yh[e])     + __half2float(yl[e]);
    float y1 = __half2float(yh[e + 1]) + __half2float(yl[e + 1]);
    float2 o; o.x = (y0 - m) * rs; o.y = (y1 - m) * rs;
    *reinterpret_cast<float2*>(&out[e]) = o;
}

// ---------------------------------------------------------------------------
// Launch
// ---------------------------------------------------------------------------
extern "C" void kernel_launch(void* const* d_in, const int* in_sizes, int n_in,
                              void* d_out, int out_size)
{
    const int*   ids = (const int*)  d_in[0];
    const float* emb = (const float*)d_in[1];
    const float* Wq  = (const float*)d_in[2];
    const float* bq  = (const float*)d_in[3];
    const float* Wk  = (const float*)d_in[4];
    const float* bk  = (const float*)d_in[5];
    const float* Wv  = (const float*)d_in[6];
    const float* bv  = (const float*)d_in[7];
    const float* Wo  = (const float*)d_in[8];
    const float* bo  = (const float*)d_in[9];
    const float* W1  = (const float*)d_in[10];
    const float* b1  = (const float*)d_in[11];
    const float* W2  = (const float*)d_in[12];
    const float* b2  = (const float*)d_in[13];

    float *bqkv, *rsqkv, *rsw1, *psum, *psq, *statsA, *statsB;
    f16 *xfh, *xfl, *x1fh, *x1fl, *qkvfh, *headf, *hf;
    f16 *wqkvfh, *wqkvfl, *wofh, *wofl, *w1f, *w2f;
    cudaGetSymbolAddress((void**)&xfh,    g_xfh);
    cudaGetSymbolAddress((void**)&xfl,    g_xfl);
    cudaGetSymbolAddress((void**)&x1fh,   g_x1fh);
    cudaGetSymbolAddress((void**)&x1fl,   g_x1fl);
    cudaGetSymbolAddress((void**)&qkvfh,  g_qkvfh);
    cudaGetSymbolAddress((void**)&headf,  g_headf);
    cudaGetSymbolAddress((void**)&hf,     g_hf);
    cudaGetSymbolAddress((void**)&wqkvfh, g_wqkvfh);
    cudaGetSymbolAddress((void**)&wqkvfl, g_wqkvfl);
    cudaGetSymbolAddress((void**)&wofh,   g_wofh);
    cudaGetSymbolAddress((void**)&wofl,   g_wofl);
    cudaGetSymbolAddress((void**)&w1f,    g_w1f);
    cudaGetSymbolAddress((void**)&w2f,    g_w2f);
    cudaGetSymbolAddress((void**)&bqkv,   g_bqkv);
    cudaGetSymbolAddress((void**)&rsqkv,  g_rsqkv);
    cudaGetSymbolAddress((void**)&rsw1,   g_rsw1);
    cudaGetSymbolAddress((void**)&psum,   g_psum);
    cudaGetSymbolAddress((void**)&psq,    g_psq);
    cudaGetSymbolAddress((void**)&statsA, g_statsA);
    cudaGetSymbolAddress((void**)&statsB, g_statsB);

    const int SM_B2_128 = 3 * (128 + 256) * SMSB * 2;   // 92160 (Wo, 2-limb B)
    const int SM_B2_64  = 3 * (128 + 128) * SMSB * 2;   // 61440 (QKV, 2-limb B)
    const int SM_B1_128 = 3 * (128 + 128) * SMSB * 2;   // 61440 (FFN, 1-limb B)
    const int SMFA      = (64 * FAS + 4 * 64 * FAS) * 2; // 46080

    cudaFuncSetAttribute((const void*)gemm2<64, 32, 32, 3, true>,
                         cudaFuncAttributeMaxDynamicSharedMemorySize, SM_B2_64);
    cudaFuncSetAttribute((const void*)gemm2<128, 64, 32, 0, true>,
                         cudaFuncAttributeMaxDynamicSharedMemorySize, SM_B2_128);
    cudaFuncSetAttribute((const void*)gemm2<128, 64, 32, 1, false>,
                         cudaFuncAttributeMaxDynamicSharedMemorySize, SM_B1_128);
    cudaFuncSetAttribute((const void*)gemm2<128, 64, 32, 0, false>,
                         cudaFuncAttributeMaxDynamicSharedMemorySize, SM_B1_128);
    cudaFuncSetAttribute((const void*)flash_attn,
                         cudaFuncAttributeMaxDynamicSharedMemorySize, SMFA);

    const float inv_div = 1.0f / 32.0f;
    const float inv_ws  = 1.0f / 1024.0f;
    dim3 tb(32, 8);

    // ---- weight prep ----
    prep_qkvw<<<(192 * DD + 255) / 256, 256>>>(Wq, Wk, Wv, bq, bk, bv);
    prep_wo<<<(DD * DKK + 255) / 256, 256>>>(Wo);
    transpose_f16c<<<dim3(DFFN / 32, DD / 32), tb>>>(W1, w1f, DD, DFFN);
    transpose_f16c<<<dim3(DD / 32, DFFN / 32), tb>>>(W2, w2f, DFFN, DD);
    colsum_kernel<<<DFFN / 256, 256>>>(W1, rsw1, DD, DFFN);

    embed_kernel<<<NTOT / 512, 256>>>(ids, emb);

    for (int it = 0; it < NREP; it++) {
        // QKV (norm_B folded): single-limb output (flash only reads hi)
        gemm2<64, 32, 32, 3, true><<<dim3(3, 128, 1), 256, SM_B2_64>>>(
            xfh, DD, wqkvfh, wqkvfl, DD, bqkv, statsB, rsqkv,
            0, 0, 0, qkvfh, 0, 192, DD, inv_ws, 0, 0);

        // flash attention (single-limb K/V)
        flash_attn<<<dim3(SS / 64, BB), 256, SMFA>>>(qkvfh, headf, inv_div);

        // y1 = head @ Wo_eff + bo + norm_B(y2-pair), pair out + LN partials
        gemm2<128, 64, 32, 0, true><<<dim3(4, 128, 1), 256, SM_B2_128>>>(
            headf, DKK, wofh, wofl, DKK, bo, 0, 0,
            xfh, xfl, statsB, x1fh, x1fl, DD, DKK, inv_ws, psum, psq);

        finalize_kernel<<<1, 256>>>(512, statsA);

        // h = relu(norm_A(y1) @ W1 + b1) — single-limb weights, alpha=1
        gemm2<128, 64, 32, 1, false><<<dim3(16, 128, 1), 256, SM_B1_128>>>(
            x1fh, DD, w1f, 0, DD, b1, statsA, rsw1,
            0, 0, 0, hf, 0, DFFN, DD, 1.0f, 0, 0);

        // y2 = h @ W2 + b2 + norm_A(y1-pair) — single-limb weights, alpha=1
        gemm2<128, 64, 32, 0, false><<<dim3(4, 128, 1), 256, SM_B1_128>>>(
            hf, DFFN, w2f, 0, DFFN, b2, 0, 0,
            x1fh, x1fl, statsA, xfh, xfl, DD, DFFN, 1.0f, psum, psq);

        finalize_kernel<<<1, 256>>>(512, statsB);
    }

    normalize_out<<<NTOT / 512, 256>>>(xfh, xfl, statsB, (float*)d_out);
}

// round 17
// speedup vs baseline: 1.3087x; 1.0159x over previous
#include <cuda_runtime.h>
#include <cuda_fp16.h>
#include <math.h>
#include <stdint.h>

#define BB   8
#define SS   2048
#define DD   512
#define DKK  64
#define DFFN 2048
#define NREP 6
#define MSROWS (BB*SS)          // 16384
#define NTOT (BB*SS*DD)         // 8388608

typedef __half f16;

// ---------------------------------------------------------------------------
// Scratch
// ---------------------------------------------------------------------------
__device__ f16 g_xfh [NTOT];    // y2 pair (post-FFN stream / embed at it 0)
__device__ f16 g_xfl [NTOT];
__device__ f16 g_x1fh[NTOT];    // y1 pair (post-attention stream)
__device__ f16 g_x1fl[NTOT];
__device__ f16 g_qkvfh[MSROWS*192];
__device__ f16 g_headf[MSROWS*DKK];
__device__ f16 g_hf[(long)MSROWS*DFFN];

__device__ f16 g_wqkvf[192*DD];     // single-limb fp16
__device__ f16 g_wof[DD*DKK];       // single-limb fp16 (Wo_eff^T)
__device__ f16 g_w1f[DFFN*DD];      // single-limb fp16
__device__ f16 g_w2f[DD*DFFN];      // single-limb fp16
__device__ float g_bqkv[192];
__device__ float g_rsqkv[192];      // per-output-col sum of combined QKV weight
__device__ float g_rsw1[DFFN];      // colsum of W1

__device__ float g_psum[1024];
__device__ float g_psq [1024];
__device__ float g_statsA[2];       // mid-LN (m, rs)
__device__ float g_statsB[2];       // post-LN (m, rs); seeded {0,1} by embed

// ---------------------------------------------------------------------------
// Helpers
// ---------------------------------------------------------------------------
__device__ __forceinline__ uint32_t cvta_shared_u32(const void* p) {
    uint32_t a;
    asm("{ .reg .u64 t; cvta.to.shared.u64 t, %1; cvt.u32.u64 %0, t; }" : "=r"(a) : "l"(p));
    return a;
}
__device__ __forceinline__ void cp_async16(uint32_t saddr, const void* gptr) {
    asm volatile("cp.async.cg.shared.global [%0], [%1], 16;" :: "r"(saddr), "l"(gptr));
}
__device__ __forceinline__ void cp_commit() {
    asm volatile("cp.async.commit_group;" ::: "memory");
}
template<int N>
__device__ __forceinline__ void cp_wait() {
    asm volatile("cp.async.wait_group %0;" :: "n"(N) : "memory");
}
__device__ __forceinline__ void ldsm_x4(uint32_t& r0, uint32_t& r1, uint32_t& r2, uint32_t& r3,
                                        uint32_t addr) {
    asm volatile("ldmatrix.sync.aligned.m8n8.x4.shared.b16 {%0,%1,%2,%3}, [%4];"
                 : "=r"(r0), "=r"(r1), "=r"(r2), "=r"(r3) : "r"(addr));
}
__device__ __forceinline__ void ldsm_x4_t(uint32_t& r0, uint32_t& r1, uint32_t& r2, uint32_t& r3,
                                          uint32_t addr) {
    asm volatile("ldmatrix.sync.aligned.m8n8.x4.trans.shared.b16 {%0,%1,%2,%3}, [%4];"
                 : "=r"(r0), "=r"(r1), "=r"(r2), "=r"(r3) : "r"(addr));
}
__device__ __forceinline__ uint32_t pack_f16(float e0, float e1) {
    uint32_t r;
    asm("cvt.rn.f16x2.f32 %0, %1, %2;" : "=r"(r) : "f"(e1), "f"(e0));
    return r;
}
__device__ __forceinline__ void split_f16p(float e0, float e1, uint32_t& hi, uint32_t& lo) {
    f16 h0 = __float2half_rn(e0);
    f16 h1 = __float2half_rn(e1);
    float l0 = e0 - __half2float(h0);
    float l1 = e1 - __half2float(h1);
    hi = ((uint32_t)__half_as_ushort(h1) << 16) | __half_as_ushort(h0);
    lo = pack_f16(l0, l1);
}
__device__ __forceinline__ void mma_f16(float* c, const uint32_t* a, const uint32_t* b) {
    asm volatile(
        "mma.sync.aligned.m16n8k16.row.col.f32.f16.f16.f32 "
        "{%0,%1,%2,%3}, {%4,%5,%6,%7}, {%8,%9}, {%0,%1,%2,%3};"
        : "+f"(c[0]), "+f"(c[1]), "+f"(c[2]), "+f"(c[3])
        : "r"(a[0]), "r"(a[1]), "r"(a[2]), "r"(a[3]), "r"(b[0]), "r"(b[1]));
}

#define SMSB 40

// ---------------------------------------------------------------------------
// Single-limb fp16 GEMM with LN folding.
// MODE 0: v = raw + bias + (src pair - m_res)*rs_res -> pair out + LN partials
// MODE 1: v = (raw - m_in*rowsum[col])*rs_in + bias, ReLU -> single out
// MODE 3: v = (raw - m_in*rowsum[col])*rs_in + bias -> single out (no ReLU)
// ---------------------------------------------------------------------------
template<int BN, int WM, int WN, int MODE>
__global__ void __launch_bounds__(256, 2)
gemm2(const f16* __restrict__ Af, int lda,
      const f16* __restrict__ Bh, int ldb,
      const float* __restrict__ bias,
      const float* __restrict__ instats, const float* __restrict__ rowsum,
      const f16* __restrict__ srch, const f16* __restrict__ srcl,
      const float* __restrict__ resstats,
      f16* __restrict__ Cf, f16* __restrict__ Cfl,
      int ldc, int K,
      float* __restrict__ psum, float* __restrict__ psq)
{
    constexpr int MT = WM / 16;
    constexpr int NT = WN / 8;
    constexpr int WARPS_N = BN / WN;
    static_assert((128 / WM) * (BN / WN) == 8, "8 warps");
    static_assert(NT % 2 == 0, "NT even");
    constexpr int STAGES = 3;
    constexpr int OFF_BH = 128 * SMSB;
    constexpr int BUFSZ  = OFF_BH + BN * SMSB;
    constexpr int BITER  = (BN * 4) / 256;

    extern __shared__ f16 smemf[];
    __shared__ float s_red0[256];
    __shared__ float s_red1[256];

    const int tid  = threadIdx.x;
    const int lane = tid & 31;
    const int wid  = tid >> 5;
    const int warp_m = wid / WARPS_N;
    const int warp_n = wid % WARPS_N;
    const int qr = lane >> 2;
    const int qc = lane & 3;

    const int m0 = blockIdx.y * 128;
    const int n0 = blockIdx.x * BN;

    float acc[MT][NT][4];
#pragma unroll
    for (int i = 0; i < MT; i++)
#pragma unroll
        for (int j = 0; j < NT; j++)
#pragma unroll
            for (int u = 0; u < 4; u++) acc[i][j][u] = 0.f;

    const uint32_t sb = cvta_shared_u32(smemf);

    auto load_chunk = [&](int c, int stg) {
        const int k0 = c << 5;
        const uint32_t base = sb + (uint32_t)stg * (BUFSZ * 2);
#pragma unroll
        for (int i = 0; i < 2; i++) {
            int idx = tid + i * 256;
            int row = idx >> 2, c8 = idx & 3;
            long g = (long)(m0 + row) * lda + k0 + c8 * 8;
            uint32_t so = (uint32_t)(row * SMSB + c8 * 8) * 2;
            cp_async16(base + so, Af + g);
        }
#pragma unroll
        for (int i = 0; i < BITER; i++) {
            int idx = tid + i * 256;
            int row = idx >> 2, c8 = idx & 3;
            long g = (long)(n0 + row) * ldb + k0 + c8 * 8;
            uint32_t so = (uint32_t)(row * SMSB + c8 * 8) * 2;
            cp_async16(base + OFF_BH * 2 + so, Bh + g);
        }
    };

    const int nch = K >> 5;
#pragma unroll
    for (int s = 0; s < STAGES - 1; s++) { load_chunk(s, s); cp_commit(); }

    const uint32_t a_off = (uint32_t)(((lane & 15) + warp_m * WM) * SMSB + (lane >> 4) * 8) * 2;
    const uint32_t b_off = (uint32_t)((((lane >> 4) & 1) * 8 + (lane & 7) + warp_n * WN) * SMSB
                                      + ((lane >> 3) & 1) * 8) * 2;

    for (int c = 0; c < nch; c++) {
        const int stg = c % STAGES;
        if (c + STAGES - 1 < nch) {
            load_chunk(c + STAGES - 1, (c + STAGES - 1) % STAGES);
            cp_commit();
            cp_wait<STAGES - 1>();
        } else {
            cp_wait<0>();
        }
        __syncthreads();

        const uint32_t stA  = sb + (uint32_t)stg * (BUFSZ * 2);
        const uint32_t stBh = stA + OFF_BH * 2;

#pragma unroll
        for (int ks = 0; ks < 2; ks++) {
            const uint32_t kk2 = (uint32_t)ks * 32;
            uint32_t bh[NT][2];
#pragma unroll
            for (int in2 = 0; in2 < NT / 2; in2++) {
                uint32_t off = b_off + (uint32_t)in2 * (16 * SMSB * 2) + kk2;
                ldsm_x4(bh[2*in2][0], bh[2*in2][1], bh[2*in2+1][0], bh[2*in2+1][1], stBh + off);
            }
#pragma unroll
            for (int im = 0; im < MT; im++) {
                uint32_t off = a_off + (uint32_t)im * (16 * SMSB * 2) + kk2;
                uint32_t ah[4];
                ldsm_x4(ah[0], ah[1], ah[2], ah[3], stA + off);
#pragma unroll
                for (int in_ = 0; in_ < NT; in_++)
                    mma_f16(acc[im][in_], ah, bh[in_]);
            }
        }
        __syncthreads();
    }

    // ---- epilogue ----
    float m_in = 0.f, rs_in = 1.f, m_res = 0.f, rs_res = 1.f;
    if (MODE == 1 || MODE == 3) { m_in = instats[0]; rs_in = instats[1]; }
    if (MODE == 0) { m_res = resstats[0]; rs_res = resstats[1]; }

    float lsum = 0.f, lsq = 0.f;
#pragma unroll
    for (int im = 0; im < MT; im++) {
#pragma unroll
        for (int h2 = 0; h2 < 2; h2++) {
            const int row = m0 + warp_m * WM + im * 16 + qr + h2 * 8;
#pragma unroll
            for (int in_ = 0; in_ < NT; in_++) {
                const int col = n0 + warp_n * WN + in_ * 8 + qc * 2;
                float raw0 = acc[im][in_][h2 * 2 + 0];
                float raw1 = acc[im][in_][h2 * 2 + 1];
                if (MODE == 0) {
                    long si = (long)row * ldc + col;
                    float y0 = __half2float(srch[si])     + __half2float(srcl[si]);
                    float y1 = __half2float(srch[si + 1]) + __half2float(srcl[si + 1]);
                    float v0 = raw0 + bias[col]     + (y0 - m_res) * rs_res;
                    float v1 = raw1 + bias[col + 1] + (y1 - m_res) * rs_res;
                    uint32_t hp, lp;
                    split_f16p(v0, v1, hp, lp);
                    *reinterpret_cast<uint32_t*>(&Cf [(long)row * ldc + col]) = hp;
                    *reinterpret_cast<uint32_t*>(&Cfl[(long)row * ldc + col]) = lp;
                    lsum += v0 + v1;
                    lsq  += v0 * v0 + v1 * v1;
                } else {
                    float v0 = (raw0 - m_in * rowsum[col])     * rs_in + bias[col];
                    float v1 = (raw1 - m_in * rowsum[col + 1]) * rs_in + bias[col + 1];
                    if (MODE == 1) { v0 = fmaxf(v0, 0.f); v1 = fmaxf(v1, 0.f); }
                    *reinterpret_cast<uint32_t*>(&Cf[(long)row * ldc + col]) = pack_f16(v0, v1);
                }
            }
        }
    }

    if (MODE == 0) {
        s_red0[tid] = lsum; s_red1[tid] = lsq;
        __syncthreads();
        for (int s = 128; s > 0; s >>= 1) {
            if (tid < s) { s_red0[tid] += s_red0[tid + s]; s_red1[tid] += s_red1[tid + s]; }
            __syncthreads();
        }
        if (tid == 0) {
            int cta = blockIdx.y * gridDim.x + blockIdx.x;
            psum[cta] = s_red0[0];
            psq [cta] = s_red1[0];
        }
    }
}

// ---------------------------------------------------------------------------
// Flash attention (single-limb everything; validated R13/R16)
// ---------------------------------------------------------------------------
#define FAS 72

__global__ void __launch_bounds__(256, 2)
flash_attn(const f16* __restrict__ qkvfh, f16* __restrict__ headf, float alpha)
{
    constexpr int QSZ = 64 * FAS;
    constexpr int CSZ = 64 * FAS;

    extern __shared__ f16 fsm[];
    const uint32_t sb = cvta_shared_u32(fsm);
    const uint32_t q_a  = sb;
    const uint32_t ck_a = sb + QSZ * 2;   // 2 bufs x {kh, vh}

    const int tid  = threadIdx.x;
    const int lane = tid & 31;
    const int wid  = tid >> 5;
    const int wrow  = wid & 3;
    const int khalf = wid >> 2;
    const int qr = lane >> 2, qc = lane & 3;
    const long bz = blockIdx.y;
    const long grow0 = bz * SS + blockIdx.x * 64;

#pragma unroll
    for (int i = 0; i < 2; i++) {
        int idx = tid + i * 256;
        int r = idx >> 3, s = idx & 7;
        long g = (grow0 + r) * 192 + s * 8;
        cp_async16(q_a + (uint32_t)(r * FAS + s * 8) * 2, qkvfh + g);
    }
    cp_commit();

    auto load_chunk = [&](int c, int buf) {
        const uint32_t base = ck_a + (uint32_t)buf * 2 * CSZ * 2;
#pragma unroll
        for (int i = 0; i < 2; i++) {
            int idx = tid + i * 256;
            int r = idx >> 3, s = idx & 7;
            long g = (bz * SS + c * 64 + r) * 192 + s * 8;
            uint32_t so = (uint32_t)(r * FAS + s * 8) * 2;
            cp_async16(base + so,           qkvfh + g + 64);
            cp_async16(base + CSZ * 2 + so, qkvfh + g + 128);
        }
        cp_commit();
    };

    load_chunk(0, 0);
    cp_wait<1>();
    __syncthreads();

    const uint32_t qa_off = (uint32_t)((lane & 15) + wrow * 16) * (FAS * 2) + (lane >> 4) * 16;
    uint32_t qa[4][4];
#pragma unroll
    for (int ks = 0; ks < 4; ks++)
        ldsm_x4(qa[ks][0], qa[ks][1], qa[ks][2], qa[ks][3], q_a + qa_off + ks * 32);

    const uint32_t kb_off = (uint32_t)(khalf * 32 + ((lane >> 4) & 1) * 8 + (lane & 7)) * (FAS * 2)
                            + ((lane >> 3) & 1) * 16;
    const uint32_t vb_off = (uint32_t)(khalf * 32 + (lane & 7) + ((lane >> 3) & 1) * 8) * (FAS * 2)
                            + ((lane >> 4) & 1) * 16;

    float o[8][4];
#pragma unroll
    for (int t = 0; t < 8; t++)
#pragma unroll
        for (int u = 0; u < 4; u++) o[t][u] = 0.f;
    float rs0 = 0.f, rs1 = 0.f;

    for (int c = 0; c < SS / 64; c++) {
        const int buf = c & 1;
        cp_wait<0>();
        __syncthreads();
        if (c + 1 < SS / 64) load_chunk(c + 1, buf ^ 1);

        const uint32_t kh_a = ck_a + (uint32_t)buf * 2 * CSZ * 2;
        const uint32_t vh_a = kh_a + CSZ * 2;

        float s[4][4];
#pragma unroll
        for (int j = 0; j < 4; j++)
#pragma unroll
            for (int u = 0; u < 4; u++) s[j][u] = 0.f;

#pragma unroll
        for (int ks = 0; ks < 4; ks++) {
            uint32_t kbh[4][2];
#pragma unroll
            for (int j4 = 0; j4 < 2; j4++) {
                uint32_t off = kb_off + (uint32_t)j4 * (16 * FAS * 2) + ks * 32;
                ldsm_x4(kbh[2*j4][0], kbh[2*j4][1], kbh[2*j4+1][0], kbh[2*j4+1][1], kh_a + off);
            }
#pragma unroll
            for (int j = 0; j < 4; j++)
                mma_f16(s[j], qa[ks], kbh[j]);
        }

        uint32_t pa[2][4];
#pragma unroll
        for (int j = 0; j < 4; j++) {
            float p0 = __expf(s[j][0] * alpha);
            float p1 = __expf(s[j][1] * alpha);
            float p2 = __expf(s[j][2] * alpha);
            float p3 = __expf(s[j][3] * alpha);
            rs0 += p0 + p1;
            rs1 += p2 + p3;
            int ks2 = j >> 1, half = (j & 1) * 2;
            pa[ks2][half + 0] = pack_f16(p0, p1);
            pa[ks2][half + 1] = pack_f16(p2, p3);
        }

#pragma unroll
        for (int ks = 0; ks < 2; ks++) {
            uint32_t vbh[8][2];
#pragma unroll
            for (int i = 0; i < 4; i++) {
                uint32_t off = vb_off + (uint32_t)ks * (16 * FAS * 2) + i * 32;
                ldsm_x4_t(vbh[2*i][0], vbh[2*i][1], vbh[2*i+1][0], vbh[2*i+1][1], vh_a + off);
            }
#pragma unroll
            for (int t = 0; t < 8; t++)
                mma_f16(o[t], pa[ks], vbh[t]);
        }
    }

    rs0 += __shfl_xor_sync(0xffffffffu, rs0, 1);
    rs0 += __shfl_xor_sync(0xffffffffu, rs0, 2);
    rs1 += __shfl_xor_sync(0xffffffffu, rs1, 1);
    rs1 += __shfl_xor_sync(0xffffffffu, rs1, 2);

    __syncthreads();
    float* sof = reinterpret_cast<float*>(fsm + QSZ);
    float4* sof4 = reinterpret_cast<float4*>(sof);
    float* zf = sof + 4 * 8 * 32 * 4;

    if (wid >= 4) {
        int base = (wid - 4) * 256;
#pragma unroll
        for (int t = 0; t < 8; t++) {
            float4 v; v.x = o[t][0]; v.y = o[t][1]; v.z = o[t][2]; v.w = o[t][3];
            sof4[base + t * 32 + lane] = v;
        }
        if (qc == 0) {
            zf[(wid - 4) * 16 + qr]     = rs0;
            zf[(wid - 4) * 16 + qr + 8] = rs1;
        }
    }
    __syncthreads();
    if (wid < 4) {
        int base = wid * 256;
#pragma unroll
        for (int t = 0; t < 8; t++) {
            float4 v = sof4[base + t * 32 + lane];
            o[t][0] += v.x; o[t][1] += v.y; o[t][2] += v.z; o[t][3] += v.w;
        }
        rs0 += zf[wid * 16 + qr];
        rs1 += zf[wid * 16 + qr + 8];
        float inv0 = 1.0f / rs0;
        float inv1 = 1.0f / rs1;
        long g0 = grow0 + wid * 16 + qr;
#pragma unroll
        for (int t = 0; t < 8; t++) {
            int col = t * 8 + qc * 2;
            *reinterpret_cast<uint32_t*>(&headf[g0 * DKK + col]) =
                pack_f16(o[t][0] * inv0, o[t][1] * inv0);
            *reinterpret_cast<uint32_t*>(&headf[(g0 + 8) * DKK + col]) =
                pack_f16(o[t][2] * inv1, o[t][3] * inv1);
        }
    }
}

// ---------------------------------------------------------------------------
// Weight prep (all single-limb fp16)
// ---------------------------------------------------------------------------
__global__ void transpose_f16c(const float* __restrict__ in, f16* __restrict__ o,
                               int R, int C_) {
    __shared__ float tt[32][33];
    int r0 = blockIdx.y * 32, c0 = blockIdx.x * 32;
#pragma unroll
    for (int i = 0; i < 32; i += 8)
        tt[threadIdx.y + i][threadIdx.x] = in[(long)(r0 + threadIdx.y + i) * C_ + c0 + threadIdx.x];
    __syncthreads();
#pragma unroll
    for (int i = 0; i < 32; i += 8) {
        long oi = (long)(c0 + threadIdx.y + i) * R + r0 + threadIdx.x;
        o[oi] = __float2half_rn(tt[threadIdx.x][threadIdx.y + i]);
    }
}

__global__ void colsum_kernel(const float* __restrict__ W, float* __restrict__ out,
                              int K, int N) {
    int n = blockIdx.x * 256 + threadIdx.x;
    if (n >= N) return;
    float s = 0.f;
    for (int k = 0; k < K; k++) s += W[(long)k * N + n];
    out[n] = s;
}

__global__ void prep_qkvw(const float* __restrict__ Wq, const float* __restrict__ Wk,
                          const float* __restrict__ Wv, const float* __restrict__ bq,
                          const float* __restrict__ bk, const float* __restrict__ bv) {
    int idx = blockIdx.x * 256 + threadIdx.x;
    if (idx < 192 * DD) {
        int n = idx >> 9, k = idx & 511;
        const float* W = (n < 64) ? Wq : ((n < 128) ? Wk : Wv);
        g_wqkvf[idx] = __float2half_rn(W[k * DKK + (n & 63)]);
    }
    if (idx < 192) {
        g_bqkv[idx] = (idx < 64) ? bq[idx] : ((idx < 128) ? bk[idx - 64] : bv[idx - 128]);
        const float* W = (idx < 64) ? Wq : ((idx < 128) ? Wk : Wv);
        float s = 0.f;
        for (int k = 0; k < DD; k++) s += W[k * DKK + (idx & 63)];
        g_rsqkv[idx] = s;
    }
}

__global__ void prep_wo(const float* __restrict__ Wo) {
    int idx = blockIdx.x * 256 + threadIdx.x;
    if (idx >= DD * DKK) return;
    int e = idx / DKK, t = idx % DKK;
    float s = 0.f;
#pragma unroll
    for (int j = 0; j < 8; j++) s += Wo[(j * DKK + t) * DD + e];
    g_wof[idx] = __float2half_rn(s);
}

// ---------------------------------------------------------------------------
// Embedding + positional encoding -> y2 pair; seeds identity stats
// ---------------------------------------------------------------------------
__global__ void embed_kernel(const int* __restrict__ ids, const float* __restrict__ emb) {
    long i2 = (long)blockIdx.x * 256 + threadIdx.x;
    if (blockIdx.x == 0 && threadIdx.x == 0) {
        g_statsB[0] = 0.0f;
        g_statsB[1] = 1.0f;
    }
    if (i2 >= NTOT / 2) return;
    long e = i2 * 2;
    int d  = (int)(e & (DD - 1));
    int bs = (int)(e >> 9);
    int s  = bs & (SS - 1);
    int id = ids[bs];
    float v0 = 0.f, v1 = 0.f;
    if (id != 0) {
        const float* er = emb + (long)id * DD;
        v0 = er[d]; v1 = er[d + 1];
    }
    double f0 = pow(10000.0, (double)d / 256.0);
    double f1 = pow(10000.0, (double)(d + 1) / 256.0);
    v0 += sinf((float)((double)s / f0));
    v1 += cosf((float)((double)s / f1));
    uint32_t hp, lp;
    split_f16p(v0, v1, hp, lp);
    *reinterpret_cast<uint32_t*>(&g_xfh[e]) = hp;
    *reinterpret_cast<uint32_t*>(&g_xfl[e]) = lp;
}

// ---------------------------------------------------------------------------
// LayerNorm finalize: partials -> (m, rs)
// ---------------------------------------------------------------------------
__global__ void finalize_kernel(int n, float* __restrict__ stats_out) {
    __shared__ double ds[256], dq[256];
    double a = 0.0, b = 0.0;
    for (int i = threadIdx.x; i < n; i += 256) {
        a += (double)g_psum[i];
        b += (double)g_psq[i];
    }
    ds[threadIdx.x] = a; dq[threadIdx.x] = b; __syncthreads();
    for (int s = 128; s > 0; s >>= 1) {
        if (threadIdx.x < s) {
            ds[threadIdx.x] += ds[threadIdx.x + s];
            dq[threadIdx.x] += dq[threadIdx.x + s];
        }
        __syncthreads();
    }
    if (threadIdx.x == 0) {
        double m = ds[0] / (double)NTOT;
        double v = dq[0] / (double)NTOT - m * m;
        stats_out[0] = (float)m;
        stats_out[1] = (float)(1.0 / sqrt(v + 1e-5));
    }
}

// final output: out = (yh + yl - m) * rs  (fp32)
__global__ void normalize_out(const f16* __restrict__ yh, const f16* __restrict__ yl,
                              const float* __restrict__ stats, float* __restrict__ out) {
    long i2 = (long)blockIdx.x * 256 + threadIdx.x;
    long e = i2 * 2;
    if (e >= NTOT) return;
    float m = stats[0], rs = stats[1];
    float y0 = __half2float(yh[e])     + __half2float(yl[e]);
    float y1 = __half2float(yh[e + 1]) + __half2float(yl[e + 1]);
    float2 o; o.x = (y0 - m) * rs; o.y = (y1 - m) * rs;
    *reinterpret_cast<float2*>(&out[e]) = o;
}

// ---------------------------------------------------------------------------
// Launch
// ---------------------------------------------------------------------------
extern "C" void kernel_launch(void* const* d_in, const int* in_sizes, int n_in,
                              void* d_out, int out_size)
{
    const int*   ids = (const int*)  d_in[0];
    const float* emb = (const float*)d_in[1];
    const float* Wq  = (const float*)d_in[2];
    const float* bq  = (const float*)d_in[3];
    const float* Wk  = (const float*)d_in[4];
    const float* bk  = (const float*)d_in[5];
    const float* Wv  = (const float*)d_in[6];
    const float* bv  = (const float*)d_in[7];
    const float* Wo  = (const float*)d_in[8];
    const float* bo  = (const float*)d_in[9];
    const float* W1  = (const float*)d_in[10];
    const float* b1  = (const float*)d_in[11];
    const float* W2  = (const float*)d_in[12];
    const float* b2  = (const float*)d_in[13];

    float *bqkv, *rsqkv, *rsw1, *psum, *psq, *statsA, *statsB;
    f16 *xfh, *xfl, *x1fh, *x1fl, *qkvfh, *headf, *hf;
    f16 *wqkvf, *wof, *w1f, *w2f;
    cudaGetSymbolAddress((void**)&xfh,    g_xfh);
    cudaGetSymbolAddress((void**)&xfl,    g_xfl);
    cudaGetSymbolAddress((void**)&x1fh,   g_x1fh);
    cudaGetSymbolAddress((void**)&x1fl,   g_x1fl);
    cudaGetSymbolAddress((void**)&qkvfh,  g_qkvfh);
    cudaGetSymbolAddress((void**)&headf,  g_headf);
    cudaGetSymbolAddress((void**)&hf,     g_hf);
    cudaGetSymbolAddress((void**)&wqkvf,  g_wqkvf);
    cudaGetSymbolAddress((void**)&wof,    g_wof);
    cudaGetSymbolAddress((void**)&w1f,    g_w1f);
    cudaGetSymbolAddress((void**)&w2f,    g_w2f);
    cudaGetSymbolAddress((void**)&bqkv,   g_bqkv);
    cudaGetSymbolAddress((void**)&rsqkv,  g_rsqkv);
    cudaGetSymbolAddress((void**)&rsw1,   g_rsw1);
    cudaGetSymbolAddress((void**)&psum,   g_psum);
    cudaGetSymbolAddress((void**)&psq,    g_psq);
    cudaGetSymbolAddress((void**)&statsA, g_statsA);
    cudaGetSymbolAddress((void**)&statsB, g_statsB);

    const int SM64  = 3 * (128 + 64)  * SMSB * 2;    // 46080 (QKV)
    const int SM128 = 3 * (128 + 128) * SMSB * 2;    // 61440 (Wo, FFN)
    const int SMFA  = (64 * FAS + 4 * 64 * FAS) * 2; // 46080

    cudaFuncSetAttribute((const void*)gemm2<64, 32, 32, 3>,
                         cudaFuncAttributeMaxDynamicSharedMemorySize, SM64);
    cudaFuncSetAttribute((const void*)gemm2<128, 64, 32, 0>,
                         cudaFuncAttributeMaxDynamicSharedMemorySize, SM128);
    cudaFuncSetAttribute((const void*)gemm2<128, 64, 32, 1>,
                         cudaFuncAttributeMaxDynamicSharedMemorySize, SM128);
    cudaFuncSetAttribute((const void*)flash_attn,
                         cudaFuncAttributeMaxDynamicSharedMemorySize, SMFA);

    const float inv_div = 1.0f / 32.0f;
    dim3 tb(32, 8);

    // ---- weight prep ----
    prep_qkvw<<<(192 * DD + 255) / 256, 256>>>(Wq, Wk, Wv, bq, bk, bv);
    prep_wo<<<(DD * DKK + 255) / 256, 256>>>(Wo);
    transpose_f16c<<<dim3(DFFN / 32, DD / 32), tb>>>(W1, w1f, DD, DFFN);
    transpose_f16c<<<dim3(DD / 32, DFFN / 32), tb>>>(W2, w2f, DFFN, DD);
    colsum_kernel<<<DFFN / 256, 256>>>(W1, rsw1, DD, DFFN);

    embed_kernel<<<NTOT / 512, 256>>>(ids, emb);

    for (int it = 0; it < NREP; it++) {
        // QKV (norm_B folded): single-limb output
        gemm2<64, 32, 32, 3><<<dim3(3, 128, 1), 256, SM64>>>(
            xfh, DD, wqkvf, DD, bqkv, statsB, rsqkv,
            0, 0, 0, qkvfh, 0, 192, DD, 0, 0);

        // flash attention
        flash_attn<<<dim3(SS / 64, BB), 256, SMFA>>>(qkvfh, headf, inv_div);

        // y1 = head @ Wo_eff + bo + norm_B(y2-pair), pair out + LN partials
        gemm2<128, 64, 32, 0><<<dim3(4, 128, 1), 256, SM128>>>(
            headf, DKK, wof, DKK, bo, 0, 0,
            xfh, xfl, statsB, x1fh, x1fl, DD, DKK, psum, psq);

        finalize_kernel<<<1, 256>>>(512, statsA);

        // h = relu(norm_A(y1) @ W1 + b1)
        gemm2<128, 64, 32, 1><<<dim3(16, 128, 1), 256, SM128>>>(
            x1fh, DD, w1f, DD, b1, statsA, rsw1,
            0, 0, 0, hf, 0, DFFN, DD, 0, 0);

        // y2 = h @ W2 + b2 + norm_A(y1-pair), pair out + LN partials
        gemm2<128, 64, 32, 0><<<dim3(4, 128, 1), 256, SM128>>>(
            hf, DFFN, w2f, DFFN, b2, 0, 0,
            x1fh, x1fl, statsA, xfh, xfl, DD, DFFN, psum, psq);

        finalize_kernel<<<1, 256>>>(512, statsB);
    }

    normalize_out<<<NTOT / 512, 256>>>(xfh, xfl, statsB, (float*)d_out);
}